// round 11
// baseline (speedup 1.0000x reference)
#include <cuda_runtime.h>
#include <cstdint>

typedef unsigned int u32;

// Opaque 1 (volatile-loaded once per thread; NVVM cannot fold it).
__device__ u32 g_one_dev = 1u;

__device__ __forceinline__ u32 load_opaque_one()
{
    volatile u32* p = &g_one_dev;
    return *p;
}

// add routed via mad.lo (R6/R7 measured win).
__device__ __forceinline__ u32 addm(u32 a, u32 one, u32 b)
{
    u32 r;
    asm("mad.lo.u32 %0, %1, %2, %3;" : "=r"(r) : "r"(a), "r"(one), "r"(b));
    return r;
}

// ============================================================================
// JAX threefry2x32 block (20 rounds), exact. (R7 form — best measured.)
// ============================================================================
__device__ __forceinline__ void tf2x32(u32 k0, u32 k1, u32 x0, u32 x1,
                                       u32 one, u32 &o0, u32 &o1)
{
    u32 k2 = k0 ^ k1 ^ 0x1BD11BDAu;
    x0 += k0; x1 += k1;
#define TF_R(r) { x0 = addm(x0, one, x1); x1 = __funnelshift_l(x1, x1, (r)); x1 ^= x0; }
    TF_R(13) TF_R(15) TF_R(26) TF_R(6)
    x0 += k1; x1 += k2 + 1u;
    TF_R(17) TF_R(29) TF_R(16) TF_R(24)
    x0 += k2; x1 += k0 + 2u;
    TF_R(13) TF_R(15) TF_R(26) TF_R(6)
    x0 += k0; x1 += k1 + 3u;
    TF_R(17) TF_R(29) TF_R(16) TF_R(24)
    x0 += k1; x1 += k2 + 4u;
    TF_R(13) TF_R(15) TF_R(26) TF_R(6)
    x0 += k2; x1 += k0 + 5u;
#undef TF_R
    o0 = x0; o1 = x1;
}

// Constexpr copy — root keys evaluated at compile time.
constexpr u32 rotl_c(u32 v, int r) { return (v << r) | (v >> (32 - r)); }
struct K2 { u32 a, b; };
constexpr K2 tf2x32_c(u32 k0, u32 k1, u32 x0, u32 x1)
{
    u32 k2 = k0 ^ k1 ^ 0x1BD11BDAu;
    x0 += k0; x1 += k1;
#define TF_C(r) { x0 += x1; x1 = rotl_c(x1, (r)); x1 ^= x0; }
    TF_C(13) TF_C(15) TF_C(26) TF_C(6)
    x0 += k1; x1 += k2 + 1u;
    TF_C(17) TF_C(29) TF_C(16) TF_C(24)
    x0 += k2; x1 += k0 + 2u;
    TF_C(13) TF_C(15) TF_C(26) TF_C(6)
    x0 += k0; x1 += k1 + 3u;
    TF_C(17) TF_C(29) TF_C(16) TF_C(24)
    x0 += k1; x1 += k2 + 4u;
    TF_C(13) TF_C(15) TF_C(26) TF_C(6)
    x0 += k2; x1 += k0 + 5u;
#undef TF_C
    return K2{x0, x1};
}

constexpr K2 KE = tf2x32_c(0u, 42u, 0u, 0u);
constexpr K2 KG = tf2x32_c(0u, 42u, 0u, 1u);
constexpr K2 KD = tf2x32_c(0u, 42u, 0u, 2u);

__device__ __forceinline__ float bits_to_f01(u32 b)
{
    return __uint_as_float((b >> 9) | 0x3f800000u) - 1.0f;
}

// XLA ErfInv (f32, Giles polynomial) — exact.
__device__ __forceinline__ float xla_erfinv(float x)
{
    float w = -log1pf(-__fmul_rn(x, x));
    float p;
    if (w < 5.0f) {
        w = __fsub_rn(w, 2.5f);
        p = 2.81022636e-08f;
        p = __fadd_rn(3.43273939e-07f,  __fmul_rn(p, w));
        p = __fadd_rn(-3.5233877e-06f,  __fmul_rn(p, w));
        p = __fadd_rn(-4.39150654e-06f, __fmul_rn(p, w));
        p = __fadd_rn(0.00021858087f,   __fmul_rn(p, w));
        p = __fadd_rn(-0.00125372503f,  __fmul_rn(p, w));
        p = __fadd_rn(-0.00417768164f,  __fmul_rn(p, w));
        p = __fadd_rn(0.246640727f,     __fmul_rn(p, w));
        p = __fadd_rn(1.50140941f,      __fmul_rn(p, w));
    } else {
        w = __fsub_rn(sqrtf(w), 3.0f);
        p = -0.000200214257f;
        p = __fadd_rn(0.000100950558f,  __fmul_rn(p, w));
        p = __fadd_rn(0.00134934322f,   __fmul_rn(p, w));
        p = __fadd_rn(-0.00367342844f,  __fmul_rn(p, w));
        p = __fadd_rn(0.00573950773f,   __fmul_rn(p, w));
        p = __fadd_rn(-0.0076224613f,   __fmul_rn(p, w));
        p = __fadd_rn(0.00943887047f,   __fmul_rn(p, w));
        p = __fadd_rn(1.00167406f,      __fmul_rn(p, w));
        p = __fadd_rn(2.83297682f,      __fmul_rn(p, w));
    }
    return __fmul_rn(p, x);
}

// fmax(lo,u) dropped: f>=0, f*2 exact => fl(f*2+lo) >= lo (monotonicity).
__device__ __forceinline__ float normal_scalar_pt(u32 k0, u32 k1, u32 one)
{
    u32 o0, o1; tf2x32(k0, k1, 0u, 0u, one, o0, o1);
    float f = bits_to_f01(o0 ^ o1);
    const float lo = -0.99999994f;
    float u = __fadd_rn(__fmul_rn(f, 2.0f), lo);
    return __fmul_rn(1.41421356237f, xla_erfinv(u));
}

__device__ __forceinline__ float uniform01_scalar_pt(u32 k0, u32 k1, u32 one)
{
    u32 o0, o1; tf2x32(k0, k1, 0u, 0u, one, o0, o1);
    return bits_to_f01(o0 ^ o1);
}

// One full Marsaglia-Tsang iteration (PRECISE decision logs). Lazy next-key.
__device__ __forceinline__ bool gamma_iter(u32 k0, u32 k1, float dd, float cc,
                                           u32 one, float &Vout)
{
    u32 xk0, xk1, uk0, uk1;
    tf2x32(k0, k1, 0u, 1u, one, xk0, xk1);   // x_key
    tf2x32(k0, k1, 0u, 2u, one, uk0, uk1);   // U_key

    float x, v;
    for (;;) {
        u32 s0, s1; tf2x32(xk0, xk1, 0u, 1u, one, s0, s1);
        x = normal_scalar_pt(s0, s1, one);
        v = __fadd_rn(1.0f, __fmul_rn(x, cc));
        if (v > 0.0f) break;
        u32 a, b; tf2x32(xk0, xk1, 0u, 0u, one, a, b); xk0 = a; xk1 = b;
    }
    float X = __fmul_rn(x, x);
    float V = __fmul_rn(__fmul_rn(v, v), v);
    float U = uniform01_scalar_pt(uk0, uk1, one);
    Vout = V;

    if (U < __fsub_rn(1.0f, __fmul_rn(0.0331f, __fmul_rn(X, X)))) return true;
    float rhs = __fadd_rn(__fmul_rn(X, 0.5f),
                __fmul_rn(dd, __fadd_rn(__fsub_rn(1.0f, V), logf(V))));
    return (logf(U) < rhs);
}

// Full gamma (boost split + loop).
__device__ float gamma_full(u32 k0, u32 k1, float dd, float cc, u32 one)
{
    { u32 a, b; tf2x32(k0, k1, 0u, 0u, one, a, b); k0 = a; k1 = b; }
    float V;
    for (;;) {
        if (gamma_iter(k0, k1, dd, cc, one, V)) break;
        u32 a, b; tf2x32(k0, k1, 0u, 0u, one, a, b); k0 = a; k1 = b;
    }
    return __fmul_rn(dd, V);
}

// ============================================================================
// Globals: tables, KL scalar, inter-kernel buffers
// ============================================================================
__device__ float  g_klsum;
__device__ float4 g_prm[4096];           // dd, cc, invbe, 0
__device__ float2 g_ls[4096];            // locs, scales
__device__ float  g_comp[8192 * 64];     // per-(n,k) component log-prob
__device__ float  g_gd[8192 * 64];       // per-(n,k) Dirichlet gammas

__device__ __forceinline__ float digammaf_(float x)
{
    float acc = 0.0f;
    while (x < 8.0f) { acc -= __fdiv_rn(1.0f, x); x += 1.0f; }
    float ix  = __fdiv_rn(1.0f, x);
    float ix2 = ix * ix;
    float s = logf(x) - 0.5f * ix
            - ix2 * (0.0833333333f - ix2 * (0.00833333333f - ix2 * 0.00396825397f));
    return s + acc;
}

__global__ void kl_kernel(const float* __restrict__ locs, const float* __restrict__ scales,
                          const float* __restrict__ alpha, const float* __restrict__ beta,
                          const float* __restrict__ counts)
{
    __shared__ float red[256];
    float acc = 0.0f;
    for (int i = threadIdx.x; i < 4096; i += 256) {
        float lc = locs[i], sc = scales[i], al = alpha[i], be = beta[i];
        acc += -logf(sc) + 0.5f * (sc * sc + lc * lc) - 0.5f;
        acc += (al - 5.0f) * digammaf_(al) - lgammaf(al) + lgammaf(5.0f)
             + 5.0f * (logf(be) - logf(5.0f)) + al * (5.0f - be) / be;
        float dd = __fsub_rn(al, 0.33333334f);
        float cc = __fdiv_rn(0.33333334f, sqrtf(dd));
        g_prm[i] = make_float4(dd, cc, __fdiv_rn(1.0f, be), 0.0f);
        g_ls[i]  = make_float2(lc, sc);
    }
    red[threadIdx.x] = acc;
    __syncthreads();
    for (int s = 128; s > 0; s >>= 1) {
        if (threadIdx.x < (unsigned)s) red[threadIdx.x] += red[threadIdx.x + s];
        __syncthreads();
    }
    if (threadIdx.x == 0) {
        float c0 = 0.0f;
        for (int k = 0; k < 64; ++k) c0 += counts[k];
        float a0 = 2.0f * 64.0f;
        float td = lgammaf(c0) - lgammaf(a0);
        float dgc0 = digammaf_(c0);
        for (int k = 0; k < 64; ++k) {
            float ck = counts[k];
            td += lgammaf(2.0f) - lgammaf(ck);
            td += (ck - 2.0f) * (digammaf_(ck) - dgc0);
        }
        g_klsum = red[0] + td;
    }
}

// ============================================================================
// Dirichlet kernel: all 8192*64 gammas, one per thread, fully dense lanes.
// jidx = n*64 + k == global thread index (matches old per-block jidx exactly).
// ============================================================================
__global__ __launch_bounds__(256) void dirichlet_kernel(const float* __restrict__ counts)
{
    const int idx = blockIdx.x * 256 + threadIdx.x;   // 0 .. 524287
    const u32 one = load_opaque_one();
    const int kk = idx & 63;
    u32 dk0, dk1; tf2x32(KD.a, KD.b, 0u, (u32)idx, one, dk0, dk1);
    float ck = __ldg(counts + kk);
    float dd = __fsub_rn(ck, 0.33333334f);
    float cc = __fdiv_rn(0.33333334f, sqrtf(dd));
    g_gd[idx] = gamma_full(dk0, dk1, dd, cc, one);
}

// ============================================================================
// Main loss kernel: phases 1/2a as R9; phase 2b drains via a per-warp smem
// queue (dense lanes) with results routed to per-component smem accumulators.
// Writes g_comp; logsumexp moved to combine_kernel.
// ============================================================================
__global__ __launch_bounds__(256, 8) void loss_kernel(
    const float* __restrict__ x)
{
    const int n = blockIdx.x;
    const int t = threadIdx.x;
    const int k = t >> 2;
    const int q = t & 3;
    const int w = t >> 5;        // warp id (0..7)
    const int ln = t & 31;       // lane

    __shared__ float s_x[64];
    __shared__ float s_zfix[64], s_lfix[64];
    // per-warp retry queue (phase 2b). Capacity 96/warp (mean demand ~14).
    __shared__ u32   qs0[8][96], qs1[8][96];
    __shared__ int   qsi[8][96];
    __shared__ float qsd[8][96];
    __shared__ int   qc[8];

    if (t < 64) { s_x[t] = x[n * 64 + t]; s_zfix[t] = 0.0f; s_lfix[t] = 0.0f; }
    if (ln == 0) qc[w] = 0;

    const u32 one = load_opaque_one();
    __syncthreads();

    // Deferred queue (registers): pending log-tests [0,nt).
    u32   qk0[16], qk1[16];
    int   qidx[16];
    float qU[16], qX[16], qV[16], qdf[16];
    int nt = 0;

    float zsum = 0.0f, lsum = 0.0f;
    const int kd_base = k * 64 + q * 16;
    const u32 i_base = (u32)n * 4096u + (u32)kd_base;

#pragma unroll 1
    for (int jj = 0; jj < 2; ++jj) {
        float rprod = 1.0f;
#pragma unroll 1
        for (int j8 = 0; j8 < 8; ++j8) {
            const int j = jj * 8 + j8;
            const int kdidx = kd_base + j;
            const u32 i = i_base + (u32)j;

            // eps[n,k,d]
            u32 e0, e1; tf2x32(KE.a, KE.b, 0u, i, one, e0, e1);
            float f = bits_to_f01(e0 ^ e1);
            const float lo = -0.99999994f;
            float u = __fadd_rn(__fmul_rn(f, 2.0f), lo);
            float eps = __fmul_rn(1.41421356237f, xla_erfinv(u));

            const float4 prm = g_prm[kdidx];
            const float2 ls  = g_ls[kdidx];
            float mu   = __fadd_rn(ls.x, __fmul_rn(ls.y, eps));
            float diff = __fsub_rn(s_x[kdidx & 63], mu);
            float diff2 = __fmul_rn(diff, diff);

            // gamma attempt
            u32 ek0, ek1, bk0, bk1, xk0, xk1, uk0, uk1;
            tf2x32(KG.a, KG.b, 0u, i, one, ek0, ek1);
            tf2x32(ek0, ek1, 0u, 0u, one, bk0, bk1);
            tf2x32(bk0, bk1, 0u, 1u, one, xk0, xk1);
            tf2x32(bk0, bk1, 0u, 2u, one, uk0, uk1);

            float xv, vv;
            for (;;) {
                u32 s0, s1; tf2x32(xk0, xk1, 0u, 1u, one, s0, s1);
                xv = normal_scalar_pt(s0, s1, one);
                vv = __fadd_rn(1.0f, __fmul_rn(xv, prm.y));
                if (vv > 0.0f) break;
                u32 a, b; tf2x32(xk0, xk1, 0u, 0u, one, a, b); xk0 = a; xk1 = b;
            }
            float X = __fmul_rn(xv, xv);
            float V = __fmul_rn(__fmul_rn(vv, vv), vv);
            float U = uniform01_scalar_pt(uk0, uk1, one);

            if (U < __fsub_rn(1.0f, __fmul_rn(0.0331f, __fmul_rn(X, X)))) {
                float r = __fmul_rn(__fmul_rn(prm.x, V), prm.z);
                zsum += __fmul_rn(diff2, r);
                rprod = __fmul_rn(rprod, r);
            } else {
                qk0[nt] = bk0; qk1[nt] = bk1;
                qidx[nt] = kdidx;
                qU[nt] = U; qX[nt] = X; qV[nt] = V;
                qdf[nt] = diff2;
                ++nt;
            }
        }
        lsum += __logf(rprod);   // value-only
    }

    // Phase 2a: dense forward sweep of pending log-tests; true rejects
    // compact to [0,wr) in the register queue (no aliasing).
    int rd = 0, wr = 0;
    while (__any_sync(0xffffffffu, rd < nt)) {
        if (rd < nt) {
            const float4 prm = g_prm[qidx[rd]];
            float V = qV[rd], dd = prm.x;
            float rhs = __fadd_rn(__fmul_rn(qX[rd], 0.5f),
                        __fmul_rn(dd, __fadd_rn(__fsub_rn(1.0f, V), logf(V))));
            if (logf(qU[rd]) < rhs) {
                float r = __fmul_rn(__fmul_rn(dd, V), prm.z);
                zsum += __fmul_rn(qdf[rd], r);
                lsum += __logf(r);
            } else {
                qk0[wr] = qk0[rd]; qk1[wr] = qk1[rd];
                qidx[wr] = qidx[rd];
                qdf[wr] = qdf[rd];
                ++wr;
            }
            ++rd;
        }
    }
    int nr = wr;

    // Phase 2b: stage retries into the per-warp smem queue, drain 32-wide.
    int base = 0;
    if (nr > 0) base = atomicAdd(&qc[w], nr);
    int staged = 0;
    if (nr > 0) { int room = 96 - base; staged = room > 0 ? (nr < room ? nr : room) : 0; }
    for (int s = 0; s < staged; ++s) {
        qs0[w][base + s] = qk0[s];
        qs1[w][base + s] = qk1[s];
        qsi[w][base + s] = qidx[s];
        qsd[w][base + s] = qdf[s];
    }
    __syncwarp();
    const int C = qc[w] < 96 ? qc[w] : 96;

    for (int pos = ln; __any_sync(0xffffffffu, pos < C); pos += 32) {
        if (pos < C) {
            u32 K0 = qs0[w][pos], K1 = qs1[w][pos];
            const int kdidx = qsi[w][pos];
            const float4 prm = g_prm[kdidx];
            float df = qsd[w][pos];
            float V;
            for (;;) {
                u32 nk0, nk1; tf2x32(K0, K1, 0u, 0u, one, nk0, nk1);
                if (gamma_iter(nk0, nk1, prm.x, prm.y, one, V)) break;
                K0 = nk0; K1 = nk1;
            }
            float r = __fmul_rn(__fmul_rn(prm.x, V), prm.z);
            const int kk = kdidx >> 6;
            atomicAdd(&s_zfix[kk], __fmul_rn(df, r));
            atomicAdd(&s_lfix[kk], __logf(r));
        }
    }

    // Fallback per-lane drain for (practically impossible) queue overflow.
    while (__any_sync(0xffffffffu, nr > staged)) {
        if (nr > staged) {
            int i2 = nr - 1;
            const float4 prm = g_prm[qidx[i2]];
            u32 nk0, nk1; tf2x32(qk0[i2], qk1[i2], 0u, 0u, one, nk0, nk1);
            float V;
            if (gamma_iter(nk0, nk1, prm.x, prm.y, one, V)) {
                float r = __fmul_rn(__fmul_rn(prm.x, V), prm.z);
                zsum += __fmul_rn(qdf[i2], r);
                lsum += __logf(r);
                nr = i2;
            } else {
                qk0[i2] = nk0; qk1[i2] = nk1;
            }
        }
    }
    __syncwarp();

    // reduce 4 lanes of component k, fold in the smem corrections
    zsum += __shfl_xor_sync(0xffffffffu, zsum, 1);
    zsum += __shfl_xor_sync(0xffffffffu, zsum, 2);
    lsum += __shfl_xor_sync(0xffffffffu, lsum, 1);
    lsum += __shfl_xor_sync(0xffffffffu, lsum, 2);

    if (q == 0) {
        float zt = zsum + s_zfix[k];
        float lt = lsum + s_lfix[k];
        // comp = -0.5*z - (sum log sigma) - 0.5*D*log(2pi); sumlogsig = -0.5*lt
        g_comp[n * 64 + k] = __fadd_rn(__fmul_rn(-0.5f, zt), __fmul_rn(0.5f, lt))
                             - 58.81206612509905f;
    }
}

// ============================================================================
// Combine kernel: one warp per n — Dirichlet normalize + logsumexp + output.
// ============================================================================
__global__ __launch_bounds__(256) void combine_kernel(float* __restrict__ out)
{
    const int gw = (blockIdx.x * 256 + threadIdx.x) >> 5;  // n (0..8191)
    const int lane = threadIdx.x & 31;
    const float* comp = g_comp + gw * 64;
    const float* gd   = g_gd   + gw * 64;

    float g0 = gd[lane], g1 = gd[lane + 32];
    float S = g0 + g1;
    for (int m = 16; m; m >>= 1) S += __shfl_xor_sync(0xffffffffu, S, m);
    float t0 = __logf(__fdiv_rn(g0, S)) + comp[lane];
    float t1 = __logf(__fdiv_rn(g1, S)) + comp[lane + 32];
    float mx = fmaxf(t0, t1);
    for (int m = 16; m; m >>= 1) mx = fmaxf(mx, __shfl_xor_sync(0xffffffffu, mx, m));
    float es = __expf(t0 - mx) + __expf(t1 - mx);
    for (int m = 16; m; m >>= 1) es += __shfl_xor_sync(0xffffffffu, es, m);
    if (lane == 0) {
        float log_lik = mx + __logf(es);
        out[gw] = g_klsum / 8192.0f - log_lik;
    }
}

// ============================================================================
extern "C" void kernel_launch(void* const* d_in, const int* in_sizes, int n_in,
                              void* d_out, int out_size)
{
    (void)in_sizes; (void)n_in; (void)out_size;
    const float* x      = (const float*)d_in[0];
    const float* locs   = (const float*)d_in[1];
    const float* scales = (const float*)d_in[2];
    const float* alpha  = (const float*)d_in[3];
    const float* beta   = (const float*)d_in[4];
    const float* counts = (const float*)d_in[5];
    float* out = (float*)d_out;

    kl_kernel<<<1, 256>>>(locs, scales, alpha, beta, counts);
    dirichlet_kernel<<<2048, 256>>>(counts);
    loss_kernel<<<8192, 256>>>(x);
    combine_kernel<<<1024, 256>>>(out);
}

// round 12
// speedup vs baseline: 1.1305x; 1.1305x over previous
#include <cuda_runtime.h>
#include <cstdint>

typedef unsigned int u32;

// Opaque 1 (volatile-loaded once per thread; NVVM cannot fold it).
__device__ u32 g_one_dev = 1u;

__device__ __forceinline__ u32 load_opaque_one()
{
    volatile u32* p = &g_one_dev;
    return *p;
}

// add routed via mad.lo (R6/R7 measured win).
__device__ __forceinline__ u32 addm(u32 a, u32 one, u32 b)
{
    u32 r;
    asm("mad.lo.u32 %0, %1, %2, %3;" : "=r"(r) : "r"(a), "r"(one), "r"(b));
    return r;
}

// ============================================================================
// JAX threefry2x32 block (20 rounds), exact. (R7 form — best measured.)
// ============================================================================
__device__ __forceinline__ void tf2x32(u32 k0, u32 k1, u32 x0, u32 x1,
                                       u32 one, u32 &o0, u32 &o1)
{
    u32 k2 = k0 ^ k1 ^ 0x1BD11BDAu;
    x0 += k0; x1 += k1;
#define TF_R(r) { x0 = addm(x0, one, x1); x1 = __funnelshift_l(x1, x1, (r)); x1 ^= x0; }
    TF_R(13) TF_R(15) TF_R(26) TF_R(6)
    x0 += k1; x1 += k2 + 1u;
    TF_R(17) TF_R(29) TF_R(16) TF_R(24)
    x0 += k2; x1 += k0 + 2u;
    TF_R(13) TF_R(15) TF_R(26) TF_R(6)
    x0 += k0; x1 += k1 + 3u;
    TF_R(17) TF_R(29) TF_R(16) TF_R(24)
    x0 += k1; x1 += k2 + 4u;
    TF_R(13) TF_R(15) TF_R(26) TF_R(6)
    x0 += k2; x1 += k0 + 5u;
#undef TF_R
    o0 = x0; o1 = x1;
}

// Constexpr copy — root keys evaluated at compile time.
constexpr u32 rotl_c(u32 v, int r) { return (v << r) | (v >> (32 - r)); }
struct K2 { u32 a, b; };
constexpr K2 tf2x32_c(u32 k0, u32 k1, u32 x0, u32 x1)
{
    u32 k2 = k0 ^ k1 ^ 0x1BD11BDAu;
    x0 += k0; x1 += k1;
#define TF_C(r) { x0 += x1; x1 = rotl_c(x1, (r)); x1 ^= x0; }
    TF_C(13) TF_C(15) TF_C(26) TF_C(6)
    x0 += k1; x1 += k2 + 1u;
    TF_C(17) TF_C(29) TF_C(16) TF_C(24)
    x0 += k2; x1 += k0 + 2u;
    TF_C(13) TF_C(15) TF_C(26) TF_C(6)
    x0 += k0; x1 += k1 + 3u;
    TF_C(17) TF_C(29) TF_C(16) TF_C(24)
    x0 += k1; x1 += k2 + 4u;
    TF_C(13) TF_C(15) TF_C(26) TF_C(6)
    x0 += k2; x1 += k0 + 5u;
#undef TF_C
    return K2{x0, x1};
}

constexpr K2 KE = tf2x32_c(0u, 42u, 0u, 0u);
constexpr K2 KG = tf2x32_c(0u, 42u, 0u, 1u);
constexpr K2 KD = tf2x32_c(0u, 42u, 0u, 2u);

__device__ __forceinline__ float bits_to_f01(u32 b)
{
    return __uint_as_float((b >> 9) | 0x3f800000u) - 1.0f;
}

// XLA ErfInv (f32, Giles) — EXACT un-contracted form. Used on the
// decision-coupled path (gamma-internal normal).
__device__ __forceinline__ float xla_erfinv(float x)
{
    float w = -log1pf(-__fmul_rn(x, x));
    float p;
    if (w < 5.0f) {
        w = __fsub_rn(w, 2.5f);
        p = 2.81022636e-08f;
        p = __fadd_rn(3.43273939e-07f,  __fmul_rn(p, w));
        p = __fadd_rn(-3.5233877e-06f,  __fmul_rn(p, w));
        p = __fadd_rn(-4.39150654e-06f, __fmul_rn(p, w));
        p = __fadd_rn(0.00021858087f,   __fmul_rn(p, w));
        p = __fadd_rn(-0.00125372503f,  __fmul_rn(p, w));
        p = __fadd_rn(-0.00417768164f,  __fmul_rn(p, w));
        p = __fadd_rn(0.246640727f,     __fmul_rn(p, w));
        p = __fadd_rn(1.50140941f,      __fmul_rn(p, w));
    } else {
        w = __fsub_rn(sqrtf(w), 3.0f);
        p = -0.000200214257f;
        p = __fadd_rn(0.000100950558f,  __fmul_rn(p, w));
        p = __fadd_rn(0.00134934322f,   __fmul_rn(p, w));
        p = __fadd_rn(-0.00367342844f,  __fmul_rn(p, w));
        p = __fadd_rn(0.00573950773f,   __fmul_rn(p, w));
        p = __fadd_rn(-0.0076224613f,   __fmul_rn(p, w));
        p = __fadd_rn(0.00943887047f,   __fmul_rn(p, w));
        p = __fadd_rn(1.00167406f,      __fmul_rn(p, w));
        p = __fadd_rn(2.83297682f,      __fmul_rn(p, w));
    }
    return __fmul_rn(p, x);
}

// FMA-contracted Giles — VALUE-ONLY path (eps). ~9 fewer instr; result
// differs from exact by <= a few ulp, which only perturbs mu/diff2.
__device__ __forceinline__ float xla_erfinv_fast(float x)
{
    float w = -log1pf(-__fmul_rn(x, x));
    float p;
    if (w < 5.0f) {
        w = __fsub_rn(w, 2.5f);
        p = 2.81022636e-08f;
        p = __fmaf_rn(p, w, 3.43273939e-07f);
        p = __fmaf_rn(p, w, -3.5233877e-06f);
        p = __fmaf_rn(p, w, -4.39150654e-06f);
        p = __fmaf_rn(p, w, 0.00021858087f);
        p = __fmaf_rn(p, w, -0.00125372503f);
        p = __fmaf_rn(p, w, -0.00417768164f);
        p = __fmaf_rn(p, w, 0.246640727f);
        p = __fmaf_rn(p, w, 1.50140941f);
    } else {
        w = __fsub_rn(sqrtf(w), 3.0f);
        p = -0.000200214257f;
        p = __fmaf_rn(p, w, 0.000100950558f);
        p = __fmaf_rn(p, w, 0.00134934322f);
        p = __fmaf_rn(p, w, -0.00367342844f);
        p = __fmaf_rn(p, w, 0.00573950773f);
        p = __fmaf_rn(p, w, -0.0076224613f);
        p = __fmaf_rn(p, w, 0.00943887047f);
        p = __fmaf_rn(p, w, 1.00167406f);
        p = __fmaf_rn(p, w, 2.83297682f);
    }
    return __fmul_rn(p, x);
}

// fmax(lo,u) dropped (exact no-op: f>=0, f*2 exact, rounding monotone).
// fma(f,2,lo) bit-identical to fl(fl(2f)+lo) since 2f exact.
__device__ __forceinline__ float normal_scalar_pt(u32 k0, u32 k1, u32 one)
{
    u32 o0, o1; tf2x32(k0, k1, 0u, 0u, one, o0, o1);
    float f = bits_to_f01(o0 ^ o1);
    float u = __fmaf_rn(f, 2.0f, -0.99999994f);
    return __fmul_rn(1.41421356237f, xla_erfinv(u));
}

__device__ __forceinline__ float uniform01_scalar_pt(u32 k0, u32 k1, u32 one)
{
    u32 o0, o1; tf2x32(k0, k1, 0u, 0u, one, o0, o1);
    return bits_to_f01(o0 ^ o1);
}

// One full Marsaglia-Tsang iteration (PRECISE decision logs). Lazy next-key.
__device__ __forceinline__ bool gamma_iter(u32 k0, u32 k1, float dd, float cc,
                                           u32 one, float &Vout)
{
    u32 xk0, xk1, uk0, uk1;
    tf2x32(k0, k1, 0u, 1u, one, xk0, xk1);   // x_key
    tf2x32(k0, k1, 0u, 2u, one, uk0, uk1);   // U_key

    float x, v;
    for (;;) {
        u32 s0, s1; tf2x32(xk0, xk1, 0u, 1u, one, s0, s1);
        x = normal_scalar_pt(s0, s1, one);
        v = __fadd_rn(1.0f, __fmul_rn(x, cc));
        if (v > 0.0f) break;
        u32 a, b; tf2x32(xk0, xk1, 0u, 0u, one, a, b); xk0 = a; xk1 = b;
    }
    float X = __fmul_rn(x, x);
    float V = __fmul_rn(__fmul_rn(v, v), v);
    float U = uniform01_scalar_pt(uk0, uk1, one);
    Vout = V;

    if (U < __fsub_rn(1.0f, __fmul_rn(0.0331f, __fmul_rn(X, X)))) return true;
    float rhs = __fadd_rn(__fmul_rn(X, 0.5f),
                __fmul_rn(dd, __fadd_rn(__fsub_rn(1.0f, V), logf(V))));
    return (logf(U) < rhs);
}

// Full gamma (boost split + loop). Dirichlet only.
__device__ float gamma_full(u32 k0, u32 k1, float dd, float cc, u32 one)
{
    { u32 a, b; tf2x32(k0, k1, 0u, 0u, one, a, b); k0 = a; k1 = b; }
    float V;
    for (;;) {
        if (gamma_iter(k0, k1, dd, cc, one, V)) break;
        u32 a, b; tf2x32(k0, k1, 0u, 0u, one, a, b); k0 = a; k1 = b;
    }
    return __fmul_rn(dd, V);
}

// ============================================================================
// Precomputed per-(k,d) tables + KL scalar
// ============================================================================
__device__ float  g_klsum;
__device__ float4 g_prm[4096];   // dd, cc, invbe, 0
__device__ float2 g_ls[4096];    // locs, scales

__device__ __forceinline__ float digammaf_(float x)
{
    float acc = 0.0f;
    while (x < 8.0f) { acc -= __fdiv_rn(1.0f, x); x += 1.0f; }
    float ix  = __fdiv_rn(1.0f, x);
    float ix2 = ix * ix;
    float s = logf(x) - 0.5f * ix
            - ix2 * (0.0833333333f - ix2 * (0.00833333333f - ix2 * 0.00396825397f));
    return s + acc;
}

__global__ void kl_kernel(const float* __restrict__ locs, const float* __restrict__ scales,
                          const float* __restrict__ alpha, const float* __restrict__ beta,
                          const float* __restrict__ counts)
{
    __shared__ float red[256];
    float acc = 0.0f;
    for (int i = threadIdx.x; i < 4096; i += 256) {
        float lc = locs[i], sc = scales[i], al = alpha[i], be = beta[i];
        acc += -logf(sc) + 0.5f * (sc * sc + lc * lc) - 0.5f;
        acc += (al - 5.0f) * digammaf_(al) - lgammaf(al) + lgammaf(5.0f)
             + 5.0f * (logf(be) - logf(5.0f)) + al * (5.0f - be) / be;
        float dd = __fsub_rn(al, 0.33333334f);
        float cc = __fdiv_rn(0.33333334f, sqrtf(dd));
        g_prm[i] = make_float4(dd, cc, __fdiv_rn(1.0f, be), 0.0f);
        g_ls[i]  = make_float2(lc, sc);
    }
    red[threadIdx.x] = acc;
    __syncthreads();
    for (int s = 128; s > 0; s >>= 1) {
        if (threadIdx.x < (unsigned)s) red[threadIdx.x] += red[threadIdx.x + s];
        __syncthreads();
    }
    if (threadIdx.x == 0) {
        float c0 = 0.0f;
        for (int k = 0; k < 64; ++k) c0 += counts[k];
        float a0 = 2.0f * 64.0f;
        float td = lgammaf(c0) - lgammaf(a0);
        float dgc0 = digammaf_(c0);
        for (int k = 0; k < 64; ++k) {
            float ck = counts[k];
            td += lgammaf(2.0f) - lgammaf(ck);
            td += (ck - 2.0f) * (digammaf_(ck) - dgc0);
        }
        g_klsum = red[0] + td;
    }
}

// ============================================================================
// Main loss kernel (exact R9 structure — best measured at 917.7us — plus the
// two micro-cuts: fmaf in u, fast erfinv on the value-only eps path).
// ============================================================================
__global__ __launch_bounds__(256, 8) void loss_kernel(
    const float* __restrict__ x, const float* __restrict__ counts,
    float* __restrict__ out)
{
    const int n = blockIdx.x;
    const int t = threadIdx.x;
    const int k = t >> 2;
    const int q = t & 3;

    __shared__ float s_x[64];
    __shared__ float s_comp[64];
    __shared__ float s_gd[64];

    if (t < 64) s_x[t] = x[n * 64 + t];

    const u32 one = load_opaque_one();
    __syncthreads();

    // Deferred queue: pending log-tests [0,nt). qU/qX/qV pending-only.
    u32   qk0[16], qk1[16];
    int   qidx[16];
    float qU[16], qX[16], qV[16], qdf[16];
    int nt = 0;

    float zsum = 0.0f, lsum = 0.0f;
    const int kd_base = k * 64 + q * 16;
    const u32 i_base = (u32)n * 4096u + (u32)kd_base;

#pragma unroll 1
    for (int jj = 0; jj < 2; ++jj) {
        float rprod = 1.0f;
#pragma unroll 1
        for (int j8 = 0; j8 < 8; ++j8) {
            const int j = jj * 8 + j8;
            const int kdidx = kd_base + j;
            const u32 i = i_base + (u32)j;

            // eps[n,k,d] — value-only: fast erfinv
            u32 e0, e1; tf2x32(KE.a, KE.b, 0u, i, one, e0, e1);
            float f = bits_to_f01(e0 ^ e1);
            float u = __fmaf_rn(f, 2.0f, -0.99999994f);
            float eps = __fmul_rn(1.41421356237f, xla_erfinv_fast(u));

            const float4 prm = g_prm[kdidx];         // dd, cc, invbe
            const float2 ls  = g_ls[kdidx];          // locs, scales
            float mu   = __fadd_rn(ls.x, __fmul_rn(ls.y, eps));
            float diff = __fsub_rn(s_x[kdidx & 63], mu);
            float diff2 = __fmul_rn(diff, diff);

            // gamma attempt
            u32 ek0, ek1, bk0, bk1, xk0, xk1, uk0, uk1;
            tf2x32(KG.a, KG.b, 0u, i, one, ek0, ek1);     // element key
            tf2x32(ek0, ek1, 0u, 0u, one, bk0, bk1);      // post-boost key
            tf2x32(bk0, bk1, 0u, 1u, one, xk0, xk1);      // x_key
            tf2x32(bk0, bk1, 0u, 2u, one, uk0, uk1);      // U_key

            float xv, vv;
            for (;;) {
                u32 s0, s1; tf2x32(xk0, xk1, 0u, 1u, one, s0, s1);
                xv = normal_scalar_pt(s0, s1, one);
                vv = __fadd_rn(1.0f, __fmul_rn(xv, prm.y));
                if (vv > 0.0f) break;
                u32 a, b; tf2x32(xk0, xk1, 0u, 0u, one, a, b); xk0 = a; xk1 = b;
            }
            float X = __fmul_rn(xv, xv);
            float V = __fmul_rn(__fmul_rn(vv, vv), vv);
            float U = uniform01_scalar_pt(uk0, uk1, one);

            if (U < __fsub_rn(1.0f, __fmul_rn(0.0331f, __fmul_rn(X, X)))) {
                float r = __fmul_rn(__fmul_rn(prm.x, V), prm.z);
                zsum += __fmul_rn(diff2, r);
                rprod = __fmul_rn(rprod, r);
            } else {
                qk0[nt] = bk0; qk1[nt] = bk1;
                qidx[nt] = kdidx;
                qU[nt] = U; qX[nt] = X; qV[nt] = V;
                qdf[nt] = diff2;
                ++nt;
            }
        }
        lsum += __logf(rprod);   // value-only
    }

    // Phase 2a: dense forward sweep of pending log-tests; rejects compact to
    // [0,wr), wr <= rd (no aliasing). Decision logs stay PRECISE.
    int rd = 0, wr = 0;
    while (__any_sync(0xffffffffu, rd < nt)) {
        if (rd < nt) {
            const float4 prm = g_prm[qidx[rd]];
            float V = qV[rd], dd = prm.x;
            float rhs = __fadd_rn(__fmul_rn(qX[rd], 0.5f),
                        __fmul_rn(dd, __fadd_rn(__fsub_rn(1.0f, V), logf(V))));
            if (logf(qU[rd]) < rhs) {
                float r = __fmul_rn(__fmul_rn(dd, V), prm.z);
                zsum += __fmul_rn(qdf[rd], r);
                lsum += __logf(r);            // value-only
            } else {
                qk0[wr] = qk0[rd]; qk1[wr] = qk1[rd];
                qidx[wr] = qidx[rd];
                qdf[wr] = qdf[rd];
                ++wr;
            }
            ++rd;
        }
    }
    int nr = wr;

    // Phase 2b: dense full-retry drain of [0,nr)
    while (__any_sync(0xffffffffu, nr > 0)) {
        if (nr > 0) {
            int i2 = nr - 1;
            const float4 prm = g_prm[qidx[i2]];
            u32 nk0, nk1; tf2x32(qk0[i2], qk1[i2], 0u, 0u, one, nk0, nk1);
            float V;
            if (gamma_iter(nk0, nk1, prm.x, prm.y, one, V)) {
                float r = __fmul_rn(__fmul_rn(prm.x, V), prm.z);
                zsum += __fmul_rn(qdf[i2], r);
                lsum += __logf(r);            // value-only
                nr = i2;
            } else {
                qk0[i2] = nk0; qk1[i2] = nk1;
            }
        }
    }

    // reduce 4 lanes of component k
    zsum += __shfl_xor_sync(0xffffffffu, zsum, 1);
    zsum += __shfl_xor_sync(0xffffffffu, zsum, 2);
    lsum += __shfl_xor_sync(0xffffffffu, lsum, 1);
    lsum += __shfl_xor_sync(0xffffffffu, lsum, 2);

    if (q == 0) {
        float sumlogsig = -0.5f * lsum;
        s_comp[k] = -0.5f * zsum - sumlogsig - 58.81206612509905f; // 0.5*D*log(2pi)
    }

    // Dirichlet gammas: dense in warps 0-1
    if (t < 64) {
        u32 jidx = (u32)n * 64u + (u32)t;
        u32 dk0, dk1; tf2x32(KD.a, KD.b, 0u, jidx, one, dk0, dk1);
        float ck = __ldg(counts + t);
        float dd = __fsub_rn(ck, 0.33333334f);
        float cc = __fdiv_rn(0.33333334f, sqrtf(dd));
        s_gd[t] = gamma_full(dk0, dk1, dd, cc, one);
    }
    __syncthreads();

    if (t < 32) {
        float g0 = s_gd[t], g1 = s_gd[t + 32];
        float S = g0 + g1;
        for (int m = 16; m; m >>= 1) S += __shfl_xor_sync(0xffffffffu, S, m);
        float t0 = __logf(__fdiv_rn(g0, S)) + s_comp[t];      // value-only
        float t1 = __logf(__fdiv_rn(g1, S)) + s_comp[t + 32]; // value-only
        float mx = fmaxf(t0, t1);
        for (int m = 16; m; m >>= 1) mx = fmaxf(mx, __shfl_xor_sync(0xffffffffu, mx, m));
        float es = __expf(t0 - mx) + __expf(t1 - mx);         // value-only
        for (int m = 16; m; m >>= 1) es += __shfl_xor_sync(0xffffffffu, es, m);
        if (t == 0) {
            float log_lik = mx + __logf(es);                  // value-only
            out[n] = g_klsum / 8192.0f - log_lik;
        }
    }
}

// ============================================================================
extern "C" void kernel_launch(void* const* d_in, const int* in_sizes, int n_in,
                              void* d_out, int out_size)
{
    (void)in_sizes; (void)n_in; (void)out_size;
    const float* x      = (const float*)d_in[0];
    const float* locs   = (const float*)d_in[1];
    const float* scales = (const float*)d_in[2];
    const float* alpha  = (const float*)d_in[3];
    const float* beta   = (const float*)d_in[4];
    const float* counts = (const float*)d_in[5];
    float* out = (float*)d_out;

    kl_kernel<<<1, 256>>>(locs, scales, alpha, beta, counts);
    loss_kernel<<<8192, 256>>>(x, counts, out);
}

// round 13
// speedup vs baseline: 1.1735x; 1.0380x over previous
#include <cuda_runtime.h>
#include <cstdint>

typedef unsigned int u32;

// Opaque 1 (volatile-loaded once per thread; NVVM cannot fold it).
__device__ u32 g_one_dev = 1u;

__device__ __forceinline__ u32 load_opaque_one()
{
    volatile u32* p = &g_one_dev;
    return *p;
}

// add routed via mad.lo (R6/R7 measured win).
__device__ __forceinline__ u32 addm(u32 a, u32 one, u32 b)
{
    u32 r;
    asm("mad.lo.u32 %0, %1, %2, %3;" : "=r"(r) : "r"(a), "r"(one), "r"(b));
    return r;
}

// ============================================================================
// JAX threefry2x32 block (20 rounds), exact. (R7 form — best measured.)
// ============================================================================
__device__ __forceinline__ void tf2x32(u32 k0, u32 k1, u32 x0, u32 x1,
                                       u32 one, u32 &o0, u32 &o1)
{
    u32 k2 = k0 ^ k1 ^ 0x1BD11BDAu;
    x0 += k0; x1 += k1;
#define TF_R(r) { x0 = addm(x0, one, x1); x1 = __funnelshift_l(x1, x1, (r)); x1 ^= x0; }
    TF_R(13) TF_R(15) TF_R(26) TF_R(6)
    x0 += k1; x1 += k2 + 1u;
    TF_R(17) TF_R(29) TF_R(16) TF_R(24)
    x0 += k2; x1 += k0 + 2u;
    TF_R(13) TF_R(15) TF_R(26) TF_R(6)
    x0 += k0; x1 += k1 + 3u;
    TF_R(17) TF_R(29) TF_R(16) TF_R(24)
    x0 += k1; x1 += k2 + 4u;
    TF_R(13) TF_R(15) TF_R(26) TF_R(6)
    x0 += k2; x1 += k0 + 5u;
#undef TF_R
    o0 = x0; o1 = x1;
}

// Constexpr copy — root keys evaluated at compile time.
constexpr u32 rotl_c(u32 v, int r) { return (v << r) | (v >> (32 - r)); }
struct K2 { u32 a, b; };
constexpr K2 tf2x32_c(u32 k0, u32 k1, u32 x0, u32 x1)
{
    u32 k2 = k0 ^ k1 ^ 0x1BD11BDAu;
    x0 += k0; x1 += k1;
#define TF_C(r) { x0 += x1; x1 = rotl_c(x1, (r)); x1 ^= x0; }
    TF_C(13) TF_C(15) TF_C(26) TF_C(6)
    x0 += k1; x1 += k2 + 1u;
    TF_C(17) TF_C(29) TF_C(16) TF_C(24)
    x0 += k2; x1 += k0 + 2u;
    TF_C(13) TF_C(15) TF_C(26) TF_C(6)
    x0 += k0; x1 += k1 + 3u;
    TF_C(17) TF_C(29) TF_C(16) TF_C(24)
    x0 += k1; x1 += k2 + 4u;
    TF_C(13) TF_C(15) TF_C(26) TF_C(6)
    x0 += k2; x1 += k0 + 5u;
#undef TF_C
    return K2{x0, x1};
}

constexpr K2 KE = tf2x32_c(0u, 42u, 0u, 0u);
constexpr K2 KG = tf2x32_c(0u, 42u, 0u, 1u);
constexpr K2 KD = tf2x32_c(0u, 42u, 0u, 2u);

__device__ __forceinline__ float bits_to_f01(u32 b)
{
    return __uint_as_float((b >> 9) | 0x3f800000u) - 1.0f;
}

// XLA ErfInv (f32, Giles) — EXACT un-contracted form (decision-coupled path).
__device__ __forceinline__ float xla_erfinv(float x)
{
    float w = -log1pf(-__fmul_rn(x, x));
    float p;
    if (w < 5.0f) {
        w = __fsub_rn(w, 2.5f);
        p = 2.81022636e-08f;
        p = __fadd_rn(3.43273939e-07f,  __fmul_rn(p, w));
        p = __fadd_rn(-3.5233877e-06f,  __fmul_rn(p, w));
        p = __fadd_rn(-4.39150654e-06f, __fmul_rn(p, w));
        p = __fadd_rn(0.00021858087f,   __fmul_rn(p, w));
        p = __fadd_rn(-0.00125372503f,  __fmul_rn(p, w));
        p = __fadd_rn(-0.00417768164f,  __fmul_rn(p, w));
        p = __fadd_rn(0.246640727f,     __fmul_rn(p, w));
        p = __fadd_rn(1.50140941f,      __fmul_rn(p, w));
    } else {
        w = __fsub_rn(sqrtf(w), 3.0f);
        p = -0.000200214257f;
        p = __fadd_rn(0.000100950558f,  __fmul_rn(p, w));
        p = __fadd_rn(0.00134934322f,   __fmul_rn(p, w));
        p = __fadd_rn(-0.00367342844f,  __fmul_rn(p, w));
        p = __fadd_rn(0.00573950773f,   __fmul_rn(p, w));
        p = __fadd_rn(-0.0076224613f,   __fmul_rn(p, w));
        p = __fadd_rn(0.00943887047f,   __fmul_rn(p, w));
        p = __fadd_rn(1.00167406f,      __fmul_rn(p, w));
        p = __fadd_rn(2.83297682f,      __fmul_rn(p, w));
    }
    return __fmul_rn(p, x);
}

// FMA-contracted Giles — VALUE-ONLY path (eps).
__device__ __forceinline__ float xla_erfinv_fast(float x)
{
    float w = -log1pf(-__fmul_rn(x, x));
    float p;
    if (w < 5.0f) {
        w = __fsub_rn(w, 2.5f);
        p = 2.81022636e-08f;
        p = __fmaf_rn(p, w, 3.43273939e-07f);
        p = __fmaf_rn(p, w, -3.5233877e-06f);
        p = __fmaf_rn(p, w, -4.39150654e-06f);
        p = __fmaf_rn(p, w, 0.00021858087f);
        p = __fmaf_rn(p, w, -0.00125372503f);
        p = __fmaf_rn(p, w, -0.00417768164f);
        p = __fmaf_rn(p, w, 0.246640727f);
        p = __fmaf_rn(p, w, 1.50140941f);
    } else {
        w = __fsub_rn(sqrtf(w), 3.0f);
        p = -0.000200214257f;
        p = __fmaf_rn(p, w, 0.000100950558f);
        p = __fmaf_rn(p, w, 0.00134934322f);
        p = __fmaf_rn(p, w, -0.00367342844f);
        p = __fmaf_rn(p, w, 0.00573950773f);
        p = __fmaf_rn(p, w, -0.0076224613f);
        p = __fmaf_rn(p, w, 0.00943887047f);
        p = __fmaf_rn(p, w, 1.00167406f);
        p = __fmaf_rn(p, w, 2.83297682f);
    }
    return __fmul_rn(p, x);
}

// Decision-coupled normal: exact forms throughout.
__device__ __forceinline__ float normal_scalar_pt(u32 k0, u32 k1, u32 one)
{
    u32 o0, o1; tf2x32(k0, k1, 0u, 0u, one, o0, o1);
    float f = bits_to_f01(o0 ^ o1);
    float u = __fmaf_rn(f, 2.0f, -0.99999994f);   // bit-identical (2f exact)
    return __fmul_rn(1.41421356237f, xla_erfinv(u));
}

__device__ __forceinline__ float uniform01_scalar_pt(u32 k0, u32 k1, u32 one)
{
    u32 o0, o1; tf2x32(k0, k1, 0u, 0u, one, o0, o1);
    return bits_to_f01(o0 ^ o1);
}

// One full Marsaglia-Tsang iteration (PRECISE decision logs). Lazy next-key.
__device__ __forceinline__ bool gamma_iter(u32 k0, u32 k1, float dd, float cc,
                                           u32 one, float &Vout)
{
    u32 xk0, xk1, uk0, uk1;
    tf2x32(k0, k1, 0u, 1u, one, xk0, xk1);   // x_key
    tf2x32(k0, k1, 0u, 2u, one, uk0, uk1);   // U_key

    float x, v;
    for (;;) {
        u32 s0, s1; tf2x32(xk0, xk1, 0u, 1u, one, s0, s1);
        x = normal_scalar_pt(s0, s1, one);
        v = __fadd_rn(1.0f, __fmul_rn(x, cc));
        if (v > 0.0f) break;
        u32 a, b; tf2x32(xk0, xk1, 0u, 0u, one, a, b); xk0 = a; xk1 = b;
    }
    float X = __fmul_rn(x, x);
    float V = __fmul_rn(__fmul_rn(v, v), v);
    float U = uniform01_scalar_pt(uk0, uk1, one);
    Vout = V;

    if (U < __fsub_rn(1.0f, __fmul_rn(0.0331f, __fmul_rn(X, X)))) return true;
    float rhs = __fadd_rn(__fmul_rn(X, 0.5f),
                __fmul_rn(dd, __fadd_rn(__fsub_rn(1.0f, V), logf(V))));
    return (logf(U) < rhs);
}

// Full gamma (boost split + loop). Dirichlet only.
__device__ float gamma_full(u32 k0, u32 k1, float dd, float cc, u32 one)
{
    { u32 a, b; tf2x32(k0, k1, 0u, 0u, one, a, b); k0 = a; k1 = b; }
    float V;
    for (;;) {
        if (gamma_iter(k0, k1, dd, cc, one, V)) break;
        u32 a, b; tf2x32(k0, k1, 0u, 0u, one, a, b); k0 = a; k1 = b;
    }
    return __fmul_rn(dd, V);
}

// ============================================================================
// Precomputed per-(k,d) tables + KL partials
// ============================================================================
__device__ float  g_klpart[17];  // [0..15] per-block KL partials, [16] theta_div
__device__ float4 g_prm[4096];   // dd, cc, invbe, 0
__device__ float2 g_ls[4096];    // locs, scales

__device__ __forceinline__ float digammaf_(float x)
{
    float acc = 0.0f;
    while (x < 8.0f) { acc -= __fdiv_rn(1.0f, x); x += 1.0f; }
    float ix  = __fdiv_rn(1.0f, x);
    float ix2 = ix * ix;
    float s = logf(x) - 0.5f * ix
            - ix2 * (0.0833333333f - ix2 * (0.00833333333f - ix2 * 0.00396825397f));
    return s + acc;
}

// Parallel KL: 16 blocks x 256 threads, one (k,d) element per thread.
// theta_div parallelized over warp 0 of block 0 (2 components per lane).
__global__ void kl_kernel(const float* __restrict__ locs, const float* __restrict__ scales,
                          const float* __restrict__ alpha, const float* __restrict__ beta,
                          const float* __restrict__ counts)
{
    __shared__ float red[256];
    const int i = blockIdx.x * 256 + threadIdx.x;

    float lc = locs[i], sc = scales[i], al = alpha[i], be = beta[i];
    float acc = -logf(sc) + 0.5f * (sc * sc + lc * lc) - 0.5f
              + (al - 5.0f) * digammaf_(al) - lgammaf(al) + lgammaf(5.0f)
              + 5.0f * (logf(be) - logf(5.0f)) + al * (5.0f - be) / be;

    float dd = __fsub_rn(al, 0.33333334f);
    float cc = __fdiv_rn(0.33333334f, sqrtf(dd));
    g_prm[i] = make_float4(dd, cc, __fdiv_rn(1.0f, be), 0.0f);
    g_ls[i]  = make_float2(lc, sc);

    red[threadIdx.x] = acc;
    __syncthreads();
    for (int s = 128; s > 0; s >>= 1) {
        if (threadIdx.x < (unsigned)s) red[threadIdx.x] += red[threadIdx.x + s];
        __syncthreads();
    }
    if (threadIdx.x == 0) g_klpart[blockIdx.x] = red[0];

    // theta_div in warp 0 of block 0 (each lane owns components t and t+32)
    if (blockIdx.x == 0 && threadIdx.x < 32) {
        const int lane = threadIdx.x;
        float c0p = counts[lane] + counts[lane + 32];
        float c0 = c0p;
        for (int m = 16; m; m >>= 1) c0 += __shfl_xor_sync(0xffffffffu, c0, m);
        float dg0 = digammaf_(c0);
        float lg2 = lgammaf(2.0f);
        float term = 0.0f;
        {
            float ck = counts[lane];
            term += lg2 - lgammaf(ck) + (ck - 2.0f) * (digammaf_(ck) - dg0);
        }
        {
            float ck = counts[lane + 32];
            term += lg2 - lgammaf(ck) + (ck - 2.0f) * (digammaf_(ck) - dg0);
        }
        for (int m = 16; m; m >>= 1) term += __shfl_xor_sync(0xffffffffu, term, m);
        if (lane == 0)
            g_klpart[16] = lgammaf(c0) - lgammaf(128.0f) + term;  // a0 = 2*64
    }
}

// ============================================================================
// Main loss kernel (R11 structure; eps u-constant fused; klsum summed from
// the 17 partials by the final thread).
// ============================================================================
__global__ __launch_bounds__(256, 8) void loss_kernel(
    const float* __restrict__ x, const float* __restrict__ counts,
    float* __restrict__ out)
{
    const int n = blockIdx.x;
    const int t = threadIdx.x;
    const int k = t >> 2;
    const int q = t & 3;

    __shared__ float s_x[64];
    __shared__ float s_comp[64];
    __shared__ float s_gd[64];

    if (t < 64) s_x[t] = x[n * 64 + t];

    const u32 one = load_opaque_one();
    __syncthreads();

    // Deferred queue: pending log-tests [0,nt). qU/qX/qV pending-only.
    u32   qk0[16], qk1[16];
    int   qidx[16];
    float qU[16], qX[16], qV[16], qdf[16];
    int nt = 0;

    float zsum = 0.0f, lsum = 0.0f;
    const int kd_base = k * 64 + q * 16;
    const u32 i_base = (u32)n * 4096u + (u32)kd_base;

#pragma unroll 1
    for (int jj = 0; jj < 2; ++jj) {
        float rprod = 1.0f;
#pragma unroll 1
        for (int j8 = 0; j8 < 8; ++j8) {
            const int j = jj * 8 + j8;
            const int kdidx = kd_base + j;
            const u32 i = i_base + (u32)j;

            // eps[n,k,d] — value-only: fused constant + fast erfinv
            u32 e0, e1; tf2x32(KE.a, KE.b, 0u, i, one, e0, e1);
            float fp = __uint_as_float((((e0 ^ e1) >> 9)) | 0x3f800000u); // [1,2)
            float u = __fmaf_rn(fp, 2.0f, -3.0f);   // ~= 2(fp-1)-0.99999994, value-only
            float eps = __fmul_rn(1.41421356237f, xla_erfinv_fast(u));

            const float4 prm = g_prm[kdidx];         // dd, cc, invbe
            const float2 ls  = g_ls[kdidx];          // locs, scales
            float mu   = __fadd_rn(ls.x, __fmul_rn(ls.y, eps));
            float diff = __fsub_rn(s_x[kdidx & 63], mu);
            float diff2 = __fmul_rn(diff, diff);

            // gamma attempt
            u32 ek0, ek1, bk0, bk1, xk0, xk1, uk0, uk1;
            tf2x32(KG.a, KG.b, 0u, i, one, ek0, ek1);     // element key
            tf2x32(ek0, ek1, 0u, 0u, one, bk0, bk1);      // post-boost key
            tf2x32(bk0, bk1, 0u, 1u, one, xk0, xk1);      // x_key
            tf2x32(bk0, bk1, 0u, 2u, one, uk0, uk1);      // U_key

            float xv, vv;
            for (;;) {
                u32 s0, s1; tf2x32(xk0, xk1, 0u, 1u, one, s0, s1);
                xv = normal_scalar_pt(s0, s1, one);
                vv = __fadd_rn(1.0f, __fmul_rn(xv, prm.y));
                if (vv > 0.0f) break;
                u32 a, b; tf2x32(xk0, xk1, 0u, 0u, one, a, b); xk0 = a; xk1 = b;
            }
            float X = __fmul_rn(xv, xv);
            float V = __fmul_rn(__fmul_rn(vv, vv), vv);
            float U = uniform01_scalar_pt(uk0, uk1, one);

            if (U < __fsub_rn(1.0f, __fmul_rn(0.0331f, __fmul_rn(X, X)))) {
                float r = __fmul_rn(__fmul_rn(prm.x, V), prm.z);
                zsum += __fmul_rn(diff2, r);
                rprod = __fmul_rn(rprod, r);
            } else {
                qk0[nt] = bk0; qk1[nt] = bk1;
                qidx[nt] = kdidx;
                qU[nt] = U; qX[nt] = X; qV[nt] = V;
                qdf[nt] = diff2;
                ++nt;
            }
        }
        lsum += __logf(rprod);   // value-only
    }

    // Phase 2a: dense forward sweep of pending log-tests; rejects compact to
    // [0,wr), wr <= rd (no aliasing). Decision logs stay PRECISE.
    int rd = 0, wr = 0;
    while (__any_sync(0xffffffffu, rd < nt)) {
        if (rd < nt) {
            const float4 prm = g_prm[qidx[rd]];
            float V = qV[rd], dd = prm.x;
            float rhs = __fadd_rn(__fmul_rn(qX[rd], 0.5f),
                        __fmul_rn(dd, __fadd_rn(__fsub_rn(1.0f, V), logf(V))));
            if (logf(qU[rd]) < rhs) {
                float r = __fmul_rn(__fmul_rn(dd, V), prm.z);
                zsum += __fmul_rn(qdf[rd], r);
                lsum += __logf(r);            // value-only
            } else {
                qk0[wr] = qk0[rd]; qk1[wr] = qk1[rd];
                qidx[wr] = qidx[rd];
                qdf[wr] = qdf[rd];
                ++wr;
            }
            ++rd;
        }
    }
    int nr = wr;

    // Phase 2b: dense full-retry drain of [0,nr)
    while (__any_sync(0xffffffffu, nr > 0)) {
        if (nr > 0) {
            int i2 = nr - 1;
            const float4 prm = g_prm[qidx[i2]];
            u32 nk0, nk1; tf2x32(qk0[i2], qk1[i2], 0u, 0u, one, nk0, nk1);
            float V;
            if (gamma_iter(nk0, nk1, prm.x, prm.y, one, V)) {
                float r = __fmul_rn(__fmul_rn(prm.x, V), prm.z);
                zsum += __fmul_rn(qdf[i2], r);
                lsum += __logf(r);            // value-only
                nr = i2;
            } else {
                qk0[i2] = nk0; qk1[i2] = nk1;
            }
        }
    }

    // reduce 4 lanes of component k
    zsum += __shfl_xor_sync(0xffffffffu, zsum, 1);
    zsum += __shfl_xor_sync(0xffffffffu, zsum, 2);
    lsum += __shfl_xor_sync(0xffffffffu, lsum, 1);
    lsum += __shfl_xor_sync(0xffffffffu, lsum, 2);

    if (q == 0) {
        float sumlogsig = -0.5f * lsum;
        s_comp[k] = -0.5f * zsum - sumlogsig - 58.81206612509905f; // 0.5*D*log(2pi)
    }

    // Dirichlet gammas: dense in warps 0-1
    if (t < 64) {
        u32 jidx = (u32)n * 64u + (u32)t;
        u32 dk0, dk1; tf2x32(KD.a, KD.b, 0u, jidx, one, dk0, dk1);
        float ck = __ldg(counts + t);
        float dd = __fsub_rn(ck, 0.33333334f);
        float cc = __fdiv_rn(0.33333334f, sqrtf(dd));
        s_gd[t] = gamma_full(dk0, dk1, dd, cc, one);
    }
    __syncthreads();

    if (t < 32) {
        float g0 = s_gd[t], g1 = s_gd[t + 32];
        float S = g0 + g1;
        for (int m = 16; m; m >>= 1) S += __shfl_xor_sync(0xffffffffu, S, m);
        float t0 = __logf(__fdiv_rn(g0, S)) + s_comp[t];      // value-only
        float t1 = __logf(__fdiv_rn(g1, S)) + s_comp[t + 32]; // value-only
        float mx = fmaxf(t0, t1);
        for (int m = 16; m; m >>= 1) mx = fmaxf(mx, __shfl_xor_sync(0xffffffffu, mx, m));
        float es = __expf(t0 - mx) + __expf(t1 - mx);         // value-only
        for (int m = 16; m; m >>= 1) es += __shfl_xor_sync(0xffffffffu, es, m);
        if (t == 0) {
            float log_lik = mx + __logf(es);                  // value-only
            float kl = 0.0f;
#pragma unroll
            for (int p = 0; p < 17; ++p) kl += g_klpart[p];
            out[n] = kl / 8192.0f - log_lik;
        }
    }
}

// ============================================================================
extern "C" void kernel_launch(void* const* d_in, const int* in_sizes, int n_in,
                              void* d_out, int out_size)
{
    (void)in_sizes; (void)n_in; (void)out_size;
    const float* x      = (const float*)d_in[0];
    const float* locs   = (const float*)d_in[1];
    const float* scales = (const float*)d_in[2];
    const float* alpha  = (const float*)d_in[3];
    const float* beta   = (const float*)d_in[4];
    const float* counts = (const float*)d_in[5];
    float* out = (float*)d_out;

    kl_kernel<<<16, 256>>>(locs, scales, alpha, beta, counts);
    loss_kernel<<<8192, 256>>>(x, counts, out);
}

// round 14
// speedup vs baseline: 1.2063x; 1.0280x over previous
#include <cuda_runtime.h>
#include <cstdint>

typedef unsigned int u32;

// Opaque 1 (volatile-loaded once per thread; NVVM cannot fold it).
__device__ u32 g_one_dev = 1u;

__device__ __forceinline__ u32 load_opaque_one()
{
    volatile u32* p = &g_one_dev;
    return *p;
}

// add routed via mad.lo (R6/R7 measured win).
__device__ __forceinline__ u32 addm(u32 a, u32 one, u32 b)
{
    u32 r;
    asm("mad.lo.u32 %0, %1, %2, %3;" : "=r"(r) : "r"(a), "r"(one), "r"(b));
    return r;
}

// ============================================================================
// JAX threefry2x32 block (20 rounds), exact. (R7 form — best measured.)
// ============================================================================
__device__ __forceinline__ void tf2x32(u32 k0, u32 k1, u32 x0, u32 x1,
                                       u32 one, u32 &o0, u32 &o1)
{
    u32 k2 = k0 ^ k1 ^ 0x1BD11BDAu;
    x0 += k0; x1 += k1;
#define TF_R(r) { x0 = addm(x0, one, x1); x1 = __funnelshift_l(x1, x1, (r)); x1 ^= x0; }
    TF_R(13) TF_R(15) TF_R(26) TF_R(6)
    x0 += k1; x1 += k2 + 1u;
    TF_R(17) TF_R(29) TF_R(16) TF_R(24)
    x0 += k2; x1 += k0 + 2u;
    TF_R(13) TF_R(15) TF_R(26) TF_R(6)
    x0 += k0; x1 += k1 + 3u;
    TF_R(17) TF_R(29) TF_R(16) TF_R(24)
    x0 += k1; x1 += k2 + 4u;
    TF_R(13) TF_R(15) TF_R(26) TF_R(6)
    x0 += k2; x1 += k0 + 5u;
#undef TF_R
    o0 = x0; o1 = x1;
}

// Constexpr copy — root keys evaluated at compile time.
constexpr u32 rotl_c(u32 v, int r) { return (v << r) | (v >> (32 - r)); }
struct K2 { u32 a, b; };
constexpr K2 tf2x32_c(u32 k0, u32 k1, u32 x0, u32 x1)
{
    u32 k2 = k0 ^ k1 ^ 0x1BD11BDAu;
    x0 += k0; x1 += k1;
#define TF_C(r) { x0 += x1; x1 = rotl_c(x1, (r)); x1 ^= x0; }
    TF_C(13) TF_C(15) TF_C(26) TF_C(6)
    x0 += k1; x1 += k2 + 1u;
    TF_C(17) TF_C(29) TF_C(16) TF_C(24)
    x0 += k2; x1 += k0 + 2u;
    TF_C(13) TF_C(15) TF_C(26) TF_C(6)
    x0 += k0; x1 += k1 + 3u;
    TF_C(17) TF_C(29) TF_C(16) TF_C(24)
    x0 += k1; x1 += k2 + 4u;
    TF_C(13) TF_C(15) TF_C(26) TF_C(6)
    x0 += k2; x1 += k0 + 5u;
#undef TF_C
    return K2{x0, x1};
}

constexpr K2 KE = tf2x32_c(0u, 42u, 0u, 0u);
constexpr K2 KG = tf2x32_c(0u, 42u, 0u, 1u);
constexpr K2 KD = tf2x32_c(0u, 42u, 0u, 2u);

__device__ __forceinline__ float bits_to_f01(u32 b)
{
    return __uint_as_float((b >> 9) | 0x3f800000u) - 1.0f;
}

// XLA ErfInv (f32, Giles) — EXACT un-contracted form (decision-coupled path).
__device__ __forceinline__ float xla_erfinv(float x)
{
    float w = -log1pf(-__fmul_rn(x, x));
    float p;
    if (w < 5.0f) {
        w = __fsub_rn(w, 2.5f);
        p = 2.81022636e-08f;
        p = __fadd_rn(3.43273939e-07f,  __fmul_rn(p, w));
        p = __fadd_rn(-3.5233877e-06f,  __fmul_rn(p, w));
        p = __fadd_rn(-4.39150654e-06f, __fmul_rn(p, w));
        p = __fadd_rn(0.00021858087f,   __fmul_rn(p, w));
        p = __fadd_rn(-0.00125372503f,  __fmul_rn(p, w));
        p = __fadd_rn(-0.00417768164f,  __fmul_rn(p, w));
        p = __fadd_rn(0.246640727f,     __fmul_rn(p, w));
        p = __fadd_rn(1.50140941f,      __fmul_rn(p, w));
    } else {
        w = __fsub_rn(sqrtf(w), 3.0f);
        p = -0.000200214257f;
        p = __fadd_rn(0.000100950558f,  __fmul_rn(p, w));
        p = __fadd_rn(0.00134934322f,   __fmul_rn(p, w));
        p = __fadd_rn(-0.00367342844f,  __fmul_rn(p, w));
        p = __fadd_rn(0.00573950773f,   __fmul_rn(p, w));
        p = __fadd_rn(-0.0076224613f,   __fmul_rn(p, w));
        p = __fadd_rn(0.00943887047f,   __fmul_rn(p, w));
        p = __fadd_rn(1.00167406f,      __fmul_rn(p, w));
        p = __fadd_rn(2.83297682f,      __fmul_rn(p, w));
    }
    return __fmul_rn(p, x);
}

// Fast Giles — VALUE-ONLY path (eps): FMA-contracted poly AND the log1pf
// replaced by MUFU-based __logf of fma(-x,x,1). ~16 fewer instr; max eps
// perturbation ~3e-3 absolute at the 2e-5-probability extreme tail, feeding
// only mu/diff2 (no accept/reject decision).
__device__ __forceinline__ float xla_erfinv_fast(float x)
{
    float w = -__logf(__fmaf_rn(-x, x, 1.0f));
    float p;
    if (w < 5.0f) {
        w = __fsub_rn(w, 2.5f);
        p = 2.81022636e-08f;
        p = __fmaf_rn(p, w, 3.43273939e-07f);
        p = __fmaf_rn(p, w, -3.5233877e-06f);
        p = __fmaf_rn(p, w, -4.39150654e-06f);
        p = __fmaf_rn(p, w, 0.00021858087f);
        p = __fmaf_rn(p, w, -0.00125372503f);
        p = __fmaf_rn(p, w, -0.00417768164f);
        p = __fmaf_rn(p, w, 0.246640727f);
        p = __fmaf_rn(p, w, 1.50140941f);
    } else {
        w = __fsub_rn(sqrtf(w), 3.0f);
        p = -0.000200214257f;
        p = __fmaf_rn(p, w, 0.000100950558f);
        p = __fmaf_rn(p, w, 0.00134934322f);
        p = __fmaf_rn(p, w, -0.00367342844f);
        p = __fmaf_rn(p, w, 0.00573950773f);
        p = __fmaf_rn(p, w, -0.0076224613f);
        p = __fmaf_rn(p, w, 0.00943887047f);
        p = __fmaf_rn(p, w, 1.00167406f);
        p = __fmaf_rn(p, w, 2.83297682f);
    }
    return __fmul_rn(p, x);
}

// Decision-coupled normal: exact forms throughout.
__device__ __forceinline__ float normal_scalar_pt(u32 k0, u32 k1, u32 one)
{
    u32 o0, o1; tf2x32(k0, k1, 0u, 0u, one, o0, o1);
    float f = bits_to_f01(o0 ^ o1);
    float u = __fmaf_rn(f, 2.0f, -0.99999994f);   // bit-identical (2f exact)
    return __fmul_rn(1.41421356237f, xla_erfinv(u));
}

__device__ __forceinline__ float uniform01_scalar_pt(u32 k0, u32 k1, u32 one)
{
    u32 o0, o1; tf2x32(k0, k1, 0u, 0u, one, o0, o1);
    return bits_to_f01(o0 ^ o1);
}

// One full Marsaglia-Tsang iteration (PRECISE decision logs). Lazy next-key.
__device__ __forceinline__ bool gamma_iter(u32 k0, u32 k1, float dd, float cc,
                                           u32 one, float &Vout)
{
    u32 xk0, xk1, uk0, uk1;
    tf2x32(k0, k1, 0u, 1u, one, xk0, xk1);   // x_key
    tf2x32(k0, k1, 0u, 2u, one, uk0, uk1);   // U_key

    float x, v;
    for (;;) {
        u32 s0, s1; tf2x32(xk0, xk1, 0u, 1u, one, s0, s1);
        x = normal_scalar_pt(s0, s1, one);
        v = __fadd_rn(1.0f, __fmul_rn(x, cc));
        if (v > 0.0f) break;
        u32 a, b; tf2x32(xk0, xk1, 0u, 0u, one, a, b); xk0 = a; xk1 = b;
    }
    float X = __fmul_rn(x, x);
    float V = __fmul_rn(__fmul_rn(v, v), v);
    float U = uniform01_scalar_pt(uk0, uk1, one);
    Vout = V;

    if (U < __fsub_rn(1.0f, __fmul_rn(0.0331f, __fmul_rn(X, X)))) return true;
    float rhs = __fadd_rn(__fmul_rn(X, 0.5f),
                __fmul_rn(dd, __fadd_rn(__fsub_rn(1.0f, V), logf(V))));
    return (logf(U) < rhs);
}

// Full gamma (boost split + loop). Dirichlet only.
__device__ float gamma_full(u32 k0, u32 k1, float dd, float cc, u32 one)
{
    { u32 a, b; tf2x32(k0, k1, 0u, 0u, one, a, b); k0 = a; k1 = b; }
    float V;
    for (;;) {
        if (gamma_iter(k0, k1, dd, cc, one, V)) break;
        u32 a, b; tf2x32(k0, k1, 0u, 0u, one, a, b); k0 = a; k1 = b;
    }
    return __fmul_rn(dd, V);
}

// ============================================================================
// Precomputed per-(k,d) tables + KL partials
// ============================================================================
__device__ float  g_klpart[17];  // [0..15] per-block KL partials, [16] theta_div
__device__ float4 g_prm[4096];   // dd, cc, invbe, 0
__device__ float2 g_ls[4096];    // locs, scales

__device__ __forceinline__ float digammaf_(float x)
{
    float acc = 0.0f;
    while (x < 8.0f) { acc -= __fdiv_rn(1.0f, x); x += 1.0f; }
    float ix  = __fdiv_rn(1.0f, x);
    float ix2 = ix * ix;
    float s = logf(x) - 0.5f * ix
            - ix2 * (0.0833333333f - ix2 * (0.00833333333f - ix2 * 0.00396825397f));
    return s + acc;
}

// Parallel KL: 16 blocks x 256 threads, one (k,d) element per thread.
// theta_div parallelized over warp 0 of block 0 (2 components per lane).
__global__ void kl_kernel(const float* __restrict__ locs, const float* __restrict__ scales,
                          const float* __restrict__ alpha, const float* __restrict__ beta,
                          const float* __restrict__ counts)
{
    __shared__ float red[256];
    const int i = blockIdx.x * 256 + threadIdx.x;

    float lc = locs[i], sc = scales[i], al = alpha[i], be = beta[i];
    float acc = -logf(sc) + 0.5f * (sc * sc + lc * lc) - 0.5f
              + (al - 5.0f) * digammaf_(al) - lgammaf(al) + lgammaf(5.0f)
              + 5.0f * (logf(be) - logf(5.0f)) + al * (5.0f - be) / be;

    float dd = __fsub_rn(al, 0.33333334f);
    float cc = __fdiv_rn(0.33333334f, sqrtf(dd));
    g_prm[i] = make_float4(dd, cc, __fdiv_rn(1.0f, be), 0.0f);
    g_ls[i]  = make_float2(lc, sc);

    red[threadIdx.x] = acc;
    __syncthreads();
    for (int s = 128; s > 0; s >>= 1) {
        if (threadIdx.x < (unsigned)s) red[threadIdx.x] += red[threadIdx.x + s];
        __syncthreads();
    }
    if (threadIdx.x == 0) g_klpart[blockIdx.x] = red[0];

    // theta_div in warp 0 of block 0 (each lane owns components t and t+32)
    if (blockIdx.x == 0 && threadIdx.x < 32) {
        const int lane = threadIdx.x;
        float c0p = counts[lane] + counts[lane + 32];
        float c0 = c0p;
        for (int m = 16; m; m >>= 1) c0 += __shfl_xor_sync(0xffffffffu, c0, m);
        float dg0 = digammaf_(c0);
        float lg2 = lgammaf(2.0f);
        float term = 0.0f;
        {
            float ck = counts[lane];
            term += lg2 - lgammaf(ck) + (ck - 2.0f) * (digammaf_(ck) - dg0);
        }
        {
            float ck = counts[lane + 32];
            term += lg2 - lgammaf(ck) + (ck - 2.0f) * (digammaf_(ck) - dg0);
        }
        for (int m = 16; m; m >>= 1) term += __shfl_xor_sync(0xffffffffu, term, m);
        if (lane == 0)
            g_klpart[16] = lgammaf(c0) - lgammaf(128.0f) + term;  // a0 = 2*64
    }
}

// ============================================================================
// Main loss kernel (R12 structure; value-only erfinv now fully MUFU-based).
// ============================================================================
__global__ __launch_bounds__(256, 8) void loss_kernel(
    const float* __restrict__ x, const float* __restrict__ counts,
    float* __restrict__ out)
{
    const int n = blockIdx.x;
    const int t = threadIdx.x;
    const int k = t >> 2;
    const int q = t & 3;

    __shared__ float s_x[64];
    __shared__ float s_comp[64];
    __shared__ float s_gd[64];

    if (t < 64) s_x[t] = x[n * 64 + t];

    const u32 one = load_opaque_one();
    __syncthreads();

    // Deferred queue: pending log-tests [0,nt). qU/qX/qV pending-only.
    u32   qk0[16], qk1[16];
    int   qidx[16];
    float qU[16], qX[16], qV[16], qdf[16];
    int nt = 0;

    float zsum = 0.0f, lsum = 0.0f;
    const int kd_base = k * 64 + q * 16;
    const u32 i_base = (u32)n * 4096u + (u32)kd_base;

#pragma unroll 1
    for (int jj = 0; jj < 2; ++jj) {
        float rprod = 1.0f;
#pragma unroll 1
        for (int j8 = 0; j8 < 8; ++j8) {
            const int j = jj * 8 + j8;
            const int kdidx = kd_base + j;
            const u32 i = i_base + (u32)j;

            // eps[n,k,d] — value-only: fused constant + fast erfinv
            u32 e0, e1; tf2x32(KE.a, KE.b, 0u, i, one, e0, e1);
            float fp = __uint_as_float((((e0 ^ e1) >> 9)) | 0x3f800000u); // [1,2)
            float u = __fmaf_rn(fp, 2.0f, -3.0f);   // ~= 2(fp-1)-0.99999994, value-only
            float eps = __fmul_rn(1.41421356237f, xla_erfinv_fast(u));

            const float4 prm = g_prm[kdidx];         // dd, cc, invbe
            const float2 ls  = g_ls[kdidx];          // locs, scales
            float mu   = __fadd_rn(ls.x, __fmul_rn(ls.y, eps));
            float diff = __fsub_rn(s_x[kdidx & 63], mu);
            float diff2 = __fmul_rn(diff, diff);

            // gamma attempt
            u32 ek0, ek1, bk0, bk1, xk0, xk1, uk0, uk1;
            tf2x32(KG.a, KG.b, 0u, i, one, ek0, ek1);     // element key
            tf2x32(ek0, ek1, 0u, 0u, one, bk0, bk1);      // post-boost key
            tf2x32(bk0, bk1, 0u, 1u, one, xk0, xk1);      // x_key
            tf2x32(bk0, bk1, 0u, 2u, one, uk0, uk1);      // U_key

            float xv, vv;
            for (;;) {
                u32 s0, s1; tf2x32(xk0, xk1, 0u, 1u, one, s0, s1);
                xv = normal_scalar_pt(s0, s1, one);
                vv = __fadd_rn(1.0f, __fmul_rn(xv, prm.y));
                if (vv > 0.0f) break;
                u32 a, b; tf2x32(xk0, xk1, 0u, 0u, one, a, b); xk0 = a; xk1 = b;
            }
            float X = __fmul_rn(xv, xv);
            float V = __fmul_rn(__fmul_rn(vv, vv), vv);
            float U = uniform01_scalar_pt(uk0, uk1, one);

            if (U < __fsub_rn(1.0f, __fmul_rn(0.0331f, __fmul_rn(X, X)))) {
                float r = __fmul_rn(__fmul_rn(prm.x, V), prm.z);
                zsum += __fmul_rn(diff2, r);
                rprod = __fmul_rn(rprod, r);
            } else {
                qk0[nt] = bk0; qk1[nt] = bk1;
                qidx[nt] = kdidx;
                qU[nt] = U; qX[nt] = X; qV[nt] = V;
                qdf[nt] = diff2;
                ++nt;
            }
        }
        lsum += __logf(rprod);   // value-only
    }

    // Phase 2a: dense forward sweep of pending log-tests; rejects compact to
    // [0,wr), wr <= rd (no aliasing). Decision logs stay PRECISE.
    int rd = 0, wr = 0;
    while (__any_sync(0xffffffffu, rd < nt)) {
        if (rd < nt) {
            const float4 prm = g_prm[qidx[rd]];
            float V = qV[rd], dd = prm.x;
            float rhs = __fadd_rn(__fmul_rn(qX[rd], 0.5f),
                        __fmul_rn(dd, __fadd_rn(__fsub_rn(1.0f, V), logf(V))));
            if (logf(qU[rd]) < rhs) {
                float r = __fmul_rn(__fmul_rn(dd, V), prm.z);
                zsum += __fmul_rn(qdf[rd], r);
                lsum += __logf(r);            // value-only
            } else {
                qk0[wr] = qk0[rd]; qk1[wr] = qk1[rd];
                qidx[wr] = qidx[rd];
                qdf[wr] = qdf[rd];
                ++wr;
            }
            ++rd;
        }
    }
    int nr = wr;

    // Phase 2b: dense full-retry drain of [0,nr)
    while (__any_sync(0xffffffffu, nr > 0)) {
        if (nr > 0) {
            int i2 = nr - 1;
            const float4 prm = g_prm[qidx[i2]];
            u32 nk0, nk1; tf2x32(qk0[i2], qk1[i2], 0u, 0u, one, nk0, nk1);
            float V;
            if (gamma_iter(nk0, nk1, prm.x, prm.y, one, V)) {
                float r = __fmul_rn(__fmul_rn(prm.x, V), prm.z);
                zsum += __fmul_rn(qdf[i2], r);
                lsum += __logf(r);            // value-only
                nr = i2;
            } else {
                qk0[i2] = nk0; qk1[i2] = nk1;
            }
        }
    }

    // reduce 4 lanes of component k
    zsum += __shfl_xor_sync(0xffffffffu, zsum, 1);
    zsum += __shfl_xor_sync(0xffffffffu, zsum, 2);
    lsum += __shfl_xor_sync(0xffffffffu, lsum, 1);
    lsum += __shfl_xor_sync(0xffffffffu, lsum, 2);

    if (q == 0) {
        float sumlogsig = -0.5f * lsum;
        s_comp[k] = -0.5f * zsum - sumlogsig - 58.81206612509905f; // 0.5*D*log(2pi)
    }

    // Dirichlet gammas: dense in warps 0-1
    if (t < 64) {
        u32 jidx = (u32)n * 64u + (u32)t;
        u32 dk0, dk1; tf2x32(KD.a, KD.b, 0u, jidx, one, dk0, dk1);
        float ck = __ldg(counts + t);
        float dd = __fsub_rn(ck, 0.33333334f);
        float cc = __fdiv_rn(0.33333334f, sqrtf(dd));
        s_gd[t] = gamma_full(dk0, dk1, dd, cc, one);
    }
    __syncthreads();

    if (t < 32) {
        float g0 = s_gd[t], g1 = s_gd[t + 32];
        float S = g0 + g1;
        for (int m = 16; m; m >>= 1) S += __shfl_xor_sync(0xffffffffu, S, m);
        float t0 = __logf(__fdiv_rn(g0, S)) + s_comp[t];      // value-only
        float t1 = __logf(__fdiv_rn(g1, S)) + s_comp[t + 32]; // value-only
        float mx = fmaxf(t0, t1);
        for (int m = 16; m; m >>= 1) mx = fmaxf(mx, __shfl_xor_sync(0xffffffffu, mx, m));
        float es = __expf(t0 - mx) + __expf(t1 - mx);         // value-only
        for (int m = 16; m; m >>= 1) es += __shfl_xor_sync(0xffffffffu, es, m);
        if (t == 0) {
            float log_lik = mx + __logf(es);                  // value-only
            float kl = 0.0f;
#pragma unroll
            for (int p = 0; p < 17; ++p) kl += g_klpart[p];
            out[n] = kl / 8192.0f - log_lik;
        }
    }
}

// ============================================================================
extern "C" void kernel_launch(void* const* d_in, const int* in_sizes, int n_in,
                              void* d_out, int out_size)
{
    (void)in_sizes; (void)n_in; (void)out_size;
    const float* x      = (const float*)d_in[0];
    const float* locs   = (const float*)d_in[1];
    const float* scales = (const float*)d_in[2];
    const float* alpha  = (const float*)d_in[3];
    const float* beta   = (const float*)d_in[4];
    const float* counts = (const float*)d_in[5];
    float* out = (float*)d_out;

    kl_kernel<<<16, 256>>>(locs, scales, alpha, beta, counts);
    loss_kernel<<<8192, 256>>>(x, counts, out);
}

// round 15
// speedup vs baseline: 1.2150x; 1.0072x over previous
#include <cuda_runtime.h>
#include <cstdint>

typedef unsigned int u32;

// Opaque 1 (volatile-loaded once per thread; NVVM cannot fold it).
__device__ u32 g_one_dev = 1u;

__device__ __forceinline__ u32 load_opaque_one()
{
    volatile u32* p = &g_one_dev;
    return *p;
}

// add routed via mad.lo (R6/R7 measured win).
__device__ __forceinline__ u32 addm(u32 a, u32 one, u32 b)
{
    u32 r;
    asm("mad.lo.u32 %0, %1, %2, %3;" : "=r"(r) : "r"(a), "r"(one), "r"(b));
    return r;
}

// ============================================================================
// JAX threefry2x32 block (20 rounds), exact. (R7 form — best measured.)
// ============================================================================
__device__ __forceinline__ void tf2x32(u32 k0, u32 k1, u32 x0, u32 x1,
                                       u32 one, u32 &o0, u32 &o1)
{
    u32 k2 = k0 ^ k1 ^ 0x1BD11BDAu;
    x0 += k0; x1 += k1;
#define TF_R(r) { x0 = addm(x0, one, x1); x1 = __funnelshift_l(x1, x1, (r)); x1 ^= x0; }
    TF_R(13) TF_R(15) TF_R(26) TF_R(6)
    x0 += k1; x1 += k2 + 1u;
    TF_R(17) TF_R(29) TF_R(16) TF_R(24)
    x0 += k2; x1 += k0 + 2u;
    TF_R(13) TF_R(15) TF_R(26) TF_R(6)
    x0 += k0; x1 += k1 + 3u;
    TF_R(17) TF_R(29) TF_R(16) TF_R(24)
    x0 += k1; x1 += k2 + 4u;
    TF_R(13) TF_R(15) TF_R(26) TF_R(6)
    x0 += k2; x1 += k0 + 5u;
#undef TF_R
    o0 = x0; o1 = x1;
}

// Constexpr copy — root keys evaluated at compile time.
constexpr u32 rotl_c(u32 v, int r) { return (v << r) | (v >> (32 - r)); }
struct K2 { u32 a, b; };
constexpr K2 tf2x32_c(u32 k0, u32 k1, u32 x0, u32 x1)
{
    u32 k2 = k0 ^ k1 ^ 0x1BD11BDAu;
    x0 += k0; x1 += k1;
#define TF_C(r) { x0 += x1; x1 = rotl_c(x1, (r)); x1 ^= x0; }
    TF_C(13) TF_C(15) TF_C(26) TF_C(6)
    x0 += k1; x1 += k2 + 1u;
    TF_C(17) TF_C(29) TF_C(16) TF_C(24)
    x0 += k2; x1 += k0 + 2u;
    TF_C(13) TF_C(15) TF_C(26) TF_C(6)
    x0 += k0; x1 += k1 + 3u;
    TF_C(17) TF_C(29) TF_C(16) TF_C(24)
    x0 += k1; x1 += k2 + 4u;
    TF_C(13) TF_C(15) TF_C(26) TF_C(6)
    x0 += k2; x1 += k0 + 5u;
#undef TF_C
    return K2{x0, x1};
}

constexpr K2 KE = tf2x32_c(0u, 42u, 0u, 0u);
constexpr K2 KG = tf2x32_c(0u, 42u, 0u, 1u);
constexpr K2 KD = tf2x32_c(0u, 42u, 0u, 2u);

__device__ __forceinline__ float bits_to_f01(u32 b)
{
    return __uint_as_float((b >> 9) | 0x3f800000u) - 1.0f;
}

// XLA ErfInv (f32, Giles) — EXACT un-contracted form (decision-coupled path).
// Must stay bit-identical to libdevice-based XLA lowering: decisions
// (v>0 / squeeze / log-test) flip otherwise.
__device__ __forceinline__ float xla_erfinv(float x)
{
    float w = -log1pf(-__fmul_rn(x, x));
    float p;
    if (w < 5.0f) {
        w = __fsub_rn(w, 2.5f);
        p = 2.81022636e-08f;
        p = __fadd_rn(3.43273939e-07f,  __fmul_rn(p, w));
        p = __fadd_rn(-3.5233877e-06f,  __fmul_rn(p, w));
        p = __fadd_rn(-4.39150654e-06f, __fmul_rn(p, w));
        p = __fadd_rn(0.00021858087f,   __fmul_rn(p, w));
        p = __fadd_rn(-0.00125372503f,  __fmul_rn(p, w));
        p = __fadd_rn(-0.00417768164f,  __fmul_rn(p, w));
        p = __fadd_rn(0.246640727f,     __fmul_rn(p, w));
        p = __fadd_rn(1.50140941f,      __fmul_rn(p, w));
    } else {
        w = __fsub_rn(sqrtf(w), 3.0f);
        p = -0.000200214257f;
        p = __fadd_rn(0.000100950558f,  __fmul_rn(p, w));
        p = __fadd_rn(0.00134934322f,   __fmul_rn(p, w));
        p = __fadd_rn(-0.00367342844f,  __fmul_rn(p, w));
        p = __fadd_rn(0.00573950773f,   __fmul_rn(p, w));
        p = __fadd_rn(-0.0076224613f,   __fmul_rn(p, w));
        p = __fadd_rn(0.00943887047f,   __fmul_rn(p, w));
        p = __fadd_rn(1.00167406f,      __fmul_rn(p, w));
        p = __fadd_rn(2.83297682f,      __fmul_rn(p, w));
    }
    return __fmul_rn(p, x);
}

// Fast Giles — VALUE-ONLY path (eps): FMA-contracted poly + MUFU log.
__device__ __forceinline__ float xla_erfinv_fast(float x)
{
    float w = -__logf(__fmaf_rn(-x, x, 1.0f));
    float p;
    if (w < 5.0f) {
        w = __fsub_rn(w, 2.5f);
        p = 2.81022636e-08f;
        p = __fmaf_rn(p, w, 3.43273939e-07f);
        p = __fmaf_rn(p, w, -3.5233877e-06f);
        p = __fmaf_rn(p, w, -4.39150654e-06f);
        p = __fmaf_rn(p, w, 0.00021858087f);
        p = __fmaf_rn(p, w, -0.00125372503f);
        p = __fmaf_rn(p, w, -0.00417768164f);
        p = __fmaf_rn(p, w, 0.246640727f);
        p = __fmaf_rn(p, w, 1.50140941f);
    } else {
        w = __fsub_rn(sqrtf(w), 3.0f);
        p = -0.000200214257f;
        p = __fmaf_rn(p, w, 0.000100950558f);
        p = __fmaf_rn(p, w, 0.00134934322f);
        p = __fmaf_rn(p, w, -0.00367342844f);
        p = __fmaf_rn(p, w, 0.00573950773f);
        p = __fmaf_rn(p, w, -0.0076224613f);
        p = __fmaf_rn(p, w, 0.00943887047f);
        p = __fmaf_rn(p, w, 1.00167406f);
        p = __fmaf_rn(p, w, 2.83297682f);
    }
    return __fmul_rn(p, x);
}

// Decision-coupled normal: exact forms throughout.
__device__ __forceinline__ float normal_scalar_pt(u32 k0, u32 k1, u32 one)
{
    u32 o0, o1; tf2x32(k0, k1, 0u, 0u, one, o0, o1);
    float f = bits_to_f01(o0 ^ o1);
    float u = __fmaf_rn(f, 2.0f, -0.99999994f);   // bit-identical (2f exact)
    return __fmul_rn(1.41421356237f, xla_erfinv(u));
}

__device__ __forceinline__ float uniform01_scalar_pt(u32 k0, u32 k1, u32 one)
{
    u32 o0, o1; tf2x32(k0, k1, 0u, 0u, one, o0, o1);
    return bits_to_f01(o0 ^ o1);
}

// One full Marsaglia-Tsang iteration (PRECISE decision logs). Lazy next-key.
__device__ __forceinline__ bool gamma_iter(u32 k0, u32 k1, float dd, float cc,
                                           u32 one, float &Vout)
{
    u32 xk0, xk1, uk0, uk1;
    tf2x32(k0, k1, 0u, 1u, one, xk0, xk1);   // x_key
    tf2x32(k0, k1, 0u, 2u, one, uk0, uk1);   // U_key

    float x, v;
    for (;;) {
        u32 s0, s1; tf2x32(xk0, xk1, 0u, 1u, one, s0, s1);
        x = normal_scalar_pt(s0, s1, one);
        v = __fadd_rn(1.0f, __fmul_rn(x, cc));
        if (v > 0.0f) break;
        u32 a, b; tf2x32(xk0, xk1, 0u, 0u, one, a, b); xk0 = a; xk1 = b;
    }
    float X = __fmul_rn(x, x);
    float V = __fmul_rn(__fmul_rn(v, v), v);
    float U = uniform01_scalar_pt(uk0, uk1, one);
    Vout = V;

    if (U < __fsub_rn(1.0f, __fmul_rn(0.0331f, __fmul_rn(X, X)))) return true;
    float rhs = __fadd_rn(__fmul_rn(X, 0.5f),
                __fmul_rn(dd, __fadd_rn(__fsub_rn(1.0f, V), logf(V))));
    return (logf(U) < rhs);
}

// Full gamma (boost split + loop). Dirichlet only.
__device__ float gamma_full(u32 k0, u32 k1, float dd, float cc, u32 one)
{
    { u32 a, b; tf2x32(k0, k1, 0u, 0u, one, a, b); k0 = a; k1 = b; }
    float V;
    for (;;) {
        if (gamma_iter(k0, k1, dd, cc, one, V)) break;
        u32 a, b; tf2x32(k0, k1, 0u, 0u, one, a, b); k0 = a; k1 = b;
    }
    return __fmul_rn(dd, V);
}

// ============================================================================
// Precomputed per-(k,d) tables + KL partials
// ============================================================================
__device__ float  g_klpart[17];  // [0..15] per-block KL partials, [16] theta_div
__device__ float4 g_prm[4096];   // dd, cc, invbe, 0
__device__ float2 g_ls[4096];    // locs, scales

__device__ __forceinline__ float digammaf_(float x)
{
    float acc = 0.0f;
    while (x < 8.0f) { acc -= __fdiv_rn(1.0f, x); x += 1.0f; }
    float ix  = __fdiv_rn(1.0f, x);
    float ix2 = ix * ix;
    float s = logf(x) - 0.5f * ix
            - ix2 * (0.0833333333f - ix2 * (0.00833333333f - ix2 * 0.00396825397f));
    return s + acc;
}

// Parallel KL: 16 blocks x 256 threads, one (k,d) element per thread.
// theta_div parallelized over warp 0 of block 0 (2 components per lane).
__global__ void kl_kernel(const float* __restrict__ locs, const float* __restrict__ scales,
                          const float* __restrict__ alpha, const float* __restrict__ beta,
                          const float* __restrict__ counts)
{
    __shared__ float red[256];
    const int i = blockIdx.x * 256 + threadIdx.x;

    float lc = locs[i], sc = scales[i], al = alpha[i], be = beta[i];
    float acc = -logf(sc) + 0.5f * (sc * sc + lc * lc) - 0.5f
              + (al - 5.0f) * digammaf_(al) - lgammaf(al) + lgammaf(5.0f)
              + 5.0f * (logf(be) - logf(5.0f)) + al * (5.0f - be) / be;

    float dd = __fsub_rn(al, 0.33333334f);
    float cc = __fdiv_rn(0.33333334f, sqrtf(dd));
    g_prm[i] = make_float4(dd, cc, __fdiv_rn(1.0f, be), 0.0f);
    g_ls[i]  = make_float2(lc, sc);

    red[threadIdx.x] = acc;
    __syncthreads();
    for (int s = 128; s > 0; s >>= 1) {
        if (threadIdx.x < (unsigned)s) red[threadIdx.x] += red[threadIdx.x + s];
        __syncthreads();
    }
    if (threadIdx.x == 0) g_klpart[blockIdx.x] = red[0];

    // theta_div in warp 0 of block 0 (each lane owns components t and t+32)
    if (blockIdx.x == 0 && threadIdx.x < 32) {
        const int lane = threadIdx.x;
        float c0p = counts[lane] + counts[lane + 32];
        float c0 = c0p;
        for (int m = 16; m; m >>= 1) c0 += __shfl_xor_sync(0xffffffffu, c0, m);
        float dg0 = digammaf_(c0);
        float lg2 = lgammaf(2.0f);
        float term = 0.0f;
        {
            float ck = counts[lane];
            term += lg2 - lgammaf(ck) + (ck - 2.0f) * (digammaf_(ck) - dg0);
        }
        {
            float ck = counts[lane + 32];
            term += lg2 - lgammaf(ck) + (ck - 2.0f) * (digammaf_(ck) - dg0);
        }
        for (int m = 16; m; m >>= 1) term += __shfl_xor_sync(0xffffffffu, term, m);
        if (lane == 0)
            g_klpart[16] = lgammaf(c0) - lgammaf(128.0f) + term;  // a0 = 2*64
    }
}

// ============================================================================
// Main loss kernel (R13 structure; single-flush rprod, phase-2 log batching).
// ============================================================================
__global__ __launch_bounds__(256, 8) void loss_kernel(
    const float* __restrict__ x, const float* __restrict__ counts,
    float* __restrict__ out)
{
    const int n = blockIdx.x;
    const int t = threadIdx.x;
    const int k = t >> 2;
    const int q = t & 3;

    __shared__ float s_x[64];
    __shared__ float s_comp[64];
    __shared__ float s_gd[64];

    if (t < 64) s_x[t] = x[n * 64 + t];

    const u32 one = load_opaque_one();
    __syncthreads();

    // Deferred queue: pending log-tests [0,nt). qU/qX/qV pending-only.
    u32   qk0[16], qk1[16];
    int   qidx[16];
    float qU[16], qX[16], qV[16], qdf[16];
    int nt = 0;

    float zsum = 0.0f, lsum = 0.0f;
    float rprod = 1.0f;   // phase-1 product of accepted r's (16-product safe:
                          // r in ~[0.03, 2.4] => product in [4e-25, 1.2e6])
    const int kd_base = k * 64 + q * 16;
    const u32 i_base = (u32)n * 4096u + (u32)kd_base;

#pragma unroll 1
    for (int j = 0; j < 16; ++j) {
        const int kdidx = kd_base + j;
        const u32 i = i_base + (u32)j;

        // eps[n,k,d] — value-only: fused constant + fast erfinv
        u32 e0, e1; tf2x32(KE.a, KE.b, 0u, i, one, e0, e1);
        float fp = __uint_as_float((((e0 ^ e1) >> 9)) | 0x3f800000u); // [1,2)
        float u = __fmaf_rn(fp, 2.0f, -3.0f);
        float eps = __fmul_rn(1.41421356237f, xla_erfinv_fast(u));

        const float4 prm = g_prm[kdidx];         // dd, cc, invbe
        const float2 ls  = g_ls[kdidx];          // locs, scales
        float mu   = __fadd_rn(ls.x, __fmul_rn(ls.y, eps));
        float diff = __fsub_rn(s_x[kdidx & 63], mu);
        float diff2 = __fmul_rn(diff, diff);

        // gamma attempt
        u32 ek0, ek1, bk0, bk1, xk0, xk1, uk0, uk1;
        tf2x32(KG.a, KG.b, 0u, i, one, ek0, ek1);     // element key
        tf2x32(ek0, ek1, 0u, 0u, one, bk0, bk1);      // post-boost key
        tf2x32(bk0, bk1, 0u, 1u, one, xk0, xk1);      // x_key
        tf2x32(bk0, bk1, 0u, 2u, one, uk0, uk1);      // U_key

        float xv, vv;
        for (;;) {
            u32 s0, s1; tf2x32(xk0, xk1, 0u, 1u, one, s0, s1);
            xv = normal_scalar_pt(s0, s1, one);
            vv = __fadd_rn(1.0f, __fmul_rn(xv, prm.y));
            if (vv > 0.0f) break;
            u32 a, b; tf2x32(xk0, xk1, 0u, 0u, one, a, b); xk0 = a; xk1 = b;
        }
        float X = __fmul_rn(xv, xv);
        float V = __fmul_rn(__fmul_rn(vv, vv), vv);
        float U = uniform01_scalar_pt(uk0, uk1, one);

        if (U < __fsub_rn(1.0f, __fmul_rn(0.0331f, __fmul_rn(X, X)))) {
            float r = __fmul_rn(__fmul_rn(prm.x, V), prm.z);
            zsum += __fmul_rn(diff2, r);
            rprod = __fmul_rn(rprod, r);
        } else {
            qk0[nt] = bk0; qk1[nt] = bk1;
            qidx[nt] = kdidx;
            qU[nt] = U; qX[nt] = X; qV[nt] = V;
            qdf[nt] = diff2;
            ++nt;
        }
    }
    lsum += __logf(rprod);   // value-only; single flush

    // Phase 2: accepted r's accumulate in rprod2, logged once at the end.
    float rprod2 = 1.0f;

    // Phase 2a: dense forward sweep of pending log-tests; rejects compact to
    // [0,wr), wr <= rd (no aliasing). Decision logs stay PRECISE.
    int rd = 0, wr = 0;
    while (__any_sync(0xffffffffu, rd < nt)) {
        if (rd < nt) {
            const float4 prm = g_prm[qidx[rd]];
            float V = qV[rd], dd = prm.x;
            float rhs = __fadd_rn(__fmul_rn(qX[rd], 0.5f),
                        __fmul_rn(dd, __fadd_rn(__fsub_rn(1.0f, V), logf(V))));
            if (logf(qU[rd]) < rhs) {
                float r = __fmul_rn(__fmul_rn(dd, V), prm.z);
                zsum += __fmul_rn(qdf[rd], r);
                rprod2 = __fmul_rn(rprod2, r);
            } else {
                qk0[wr] = qk0[rd]; qk1[wr] = qk1[rd];
                qidx[wr] = qidx[rd];
                qdf[wr] = qdf[rd];
                ++wr;
            }
            ++rd;
        }
    }
    int nr = wr;

    // Phase 2b: dense full-retry drain of [0,nr)
    while (__any_sync(0xffffffffu, nr > 0)) {
        if (nr > 0) {
            int i2 = nr - 1;
            const float4 prm = g_prm[qidx[i2]];
            u32 nk0, nk1; tf2x32(qk0[i2], qk1[i2], 0u, 0u, one, nk0, nk1);
            float V;
            if (gamma_iter(nk0, nk1, prm.x, prm.y, one, V)) {
                float r = __fmul_rn(__fmul_rn(prm.x, V), prm.z);
                zsum += __fmul_rn(qdf[i2], r);
                rprod2 = __fmul_rn(rprod2, r);
                nr = i2;
            } else {
                qk0[i2] = nk0; qk1[i2] = nk1;
            }
        }
    }
    lsum += __logf(rprod2);   // __logf(1)=0 exactly for empty threads

    // reduce 4 lanes of component k
    zsum += __shfl_xor_sync(0xffffffffu, zsum, 1);
    zsum += __shfl_xor_sync(0xffffffffu, zsum, 2);
    lsum += __shfl_xor_sync(0xffffffffu, lsum, 1);
    lsum += __shfl_xor_sync(0xffffffffu, lsum, 2);

    if (q == 0) {
        float sumlogsig = -0.5f * lsum;
        s_comp[k] = -0.5f * zsum - sumlogsig - 58.81206612509905f; // 0.5*D*log(2pi)
    }

    // Dirichlet gammas: dense in warps 0-1
    if (t < 64) {
        u32 jidx = (u32)n * 64u + (u32)t;
        u32 dk0, dk1; tf2x32(KD.a, KD.b, 0u, jidx, one, dk0, dk1);
        float ck = __ldg(counts + t);
        float dd = __fsub_rn(ck, 0.33333334f);
        float cc = __fdiv_rn(0.33333334f, sqrtf(dd));
        s_gd[t] = gamma_full(dk0, dk1, dd, cc, one);
    }
    __syncthreads();

    if (t < 32) {
        float g0 = s_gd[t], g1 = s_gd[t + 32];
        float S = g0 + g1;
        for (int m = 16; m; m >>= 1) S += __shfl_xor_sync(0xffffffffu, S, m);
        float t0 = __logf(__fdiv_rn(g0, S)) + s_comp[t];      // value-only
        float t1 = __logf(__fdiv_rn(g1, S)) + s_comp[t + 32]; // value-only
        float mx = fmaxf(t0, t1);
        for (int m = 16; m; m >>= 1) mx = fmaxf(mx, __shfl_xor_sync(0xffffffffu, mx, m));
        float es = __expf(t0 - mx) + __expf(t1 - mx);         // value-only
        for (int m = 16; m; m >>= 1) es += __shfl_xor_sync(0xffffffffu, es, m);
        if (t == 0) {
            float log_lik = mx + __logf(es);                  // value-only
            float kl = 0.0f;
#pragma unroll
            for (int p = 0; p < 17; ++p) kl += g_klpart[p];
            out[n] = kl / 8192.0f - log_lik;
        }
    }
}

// ============================================================================
extern "C" void kernel_launch(void* const* d_in, const int* in_sizes, int n_in,
                              void* d_out, int out_size)
{
    (void)in_sizes; (void)n_in; (void)out_size;
    const float* x      = (const float*)d_in[0];
    const float* locs   = (const float*)d_in[1];
    const float* scales = (const float*)d_in[2];
    const float* alpha  = (const float*)d_in[3];
    const float* beta   = (const float*)d_in[4];
    const float* counts = (const float*)d_in[5];
    float* out = (float*)d_out;

    kl_kernel<<<16, 256>>>(locs, scales, alpha, beta, counts);
    loss_kernel<<<8192, 256>>>(x, counts, out);
}

// round 16
// speedup vs baseline: 1.2174x; 1.0020x over previous
#include <cuda_runtime.h>
#include <cstdint>

typedef unsigned int u32;

// Opaque 1 (volatile-loaded once per thread; NVVM cannot fold it).
__device__ u32 g_one_dev = 1u;

__device__ __forceinline__ u32 load_opaque_one()
{
    volatile u32* p = &g_one_dev;
    return *p;
}

// add routed via mad.lo (R6/R7 measured win).
__device__ __forceinline__ u32 addm(u32 a, u32 one, u32 b)
{
    u32 r;
    asm("mad.lo.u32 %0, %1, %2, %3;" : "=r"(r) : "r"(a), "r"(one), "r"(b));
    return r;
}

// ============================================================================
// JAX threefry2x32 block (20 rounds), exact. (R7 form — best measured.)
// ============================================================================
__device__ __forceinline__ void tf2x32(u32 k0, u32 k1, u32 x0, u32 x1,
                                       u32 one, u32 &o0, u32 &o1)
{
    u32 k2 = k0 ^ k1 ^ 0x1BD11BDAu;
    x0 += k0; x1 += k1;
#define TF_R(r) { x0 = addm(x0, one, x1); x1 = __funnelshift_l(x1, x1, (r)); x1 ^= x0; }
    TF_R(13) TF_R(15) TF_R(26) TF_R(6)
    x0 += k1; x1 += k2 + 1u;
    TF_R(17) TF_R(29) TF_R(16) TF_R(24)
    x0 += k2; x1 += k0 + 2u;
    TF_R(13) TF_R(15) TF_R(26) TF_R(6)
    x0 += k0; x1 += k1 + 3u;
    TF_R(17) TF_R(29) TF_R(16) TF_R(24)
    x0 += k1; x1 += k2 + 4u;
    TF_R(13) TF_R(15) TF_R(26) TF_R(6)
    x0 += k2; x1 += k0 + 5u;
#undef TF_R
    o0 = x0; o1 = x1;
}

// Constexpr copy — root keys evaluated at compile time.
constexpr u32 rotl_c(u32 v, int r) { return (v << r) | (v >> (32 - r)); }
struct K2 { u32 a, b; };
constexpr K2 tf2x32_c(u32 k0, u32 k1, u32 x0, u32 x1)
{
    u32 k2 = k0 ^ k1 ^ 0x1BD11BDAu;
    x0 += k0; x1 += k1;
#define TF_C(r) { x0 += x1; x1 = rotl_c(x1, (r)); x1 ^= x0; }
    TF_C(13) TF_C(15) TF_C(26) TF_C(6)
    x0 += k1; x1 += k2 + 1u;
    TF_C(17) TF_C(29) TF_C(16) TF_C(24)
    x0 += k2; x1 += k0 + 2u;
    TF_C(13) TF_C(15) TF_C(26) TF_C(6)
    x0 += k0; x1 += k1 + 3u;
    TF_C(17) TF_C(29) TF_C(16) TF_C(24)
    x0 += k1; x1 += k2 + 4u;
    TF_C(13) TF_C(15) TF_C(26) TF_C(6)
    x0 += k2; x1 += k0 + 5u;
#undef TF_C
    return K2{x0, x1};
}

constexpr K2 KE = tf2x32_c(0u, 42u, 0u, 0u);
constexpr K2 KG = tf2x32_c(0u, 42u, 0u, 1u);
constexpr K2 KD = tf2x32_c(0u, 42u, 0u, 2u);

__device__ __forceinline__ float bits_to_f01(u32 b)
{
    return __uint_as_float((b >> 9) | 0x3f800000u) - 1.0f;
}

// XLA ErfInv (f32, Giles) — EXACT un-contracted form (decision-coupled path).
__device__ __forceinline__ float xla_erfinv(float x)
{
    float w = -log1pf(-__fmul_rn(x, x));
    float p;
    if (w < 5.0f) {
        w = __fsub_rn(w, 2.5f);
        p = 2.81022636e-08f;
        p = __fadd_rn(3.43273939e-07f,  __fmul_rn(p, w));
        p = __fadd_rn(-3.5233877e-06f,  __fmul_rn(p, w));
        p = __fadd_rn(-4.39150654e-06f, __fmul_rn(p, w));
        p = __fadd_rn(0.00021858087f,   __fmul_rn(p, w));
        p = __fadd_rn(-0.00125372503f,  __fmul_rn(p, w));
        p = __fadd_rn(-0.00417768164f,  __fmul_rn(p, w));
        p = __fadd_rn(0.246640727f,     __fmul_rn(p, w));
        p = __fadd_rn(1.50140941f,      __fmul_rn(p, w));
    } else {
        w = __fsub_rn(sqrtf(w), 3.0f);
        p = -0.000200214257f;
        p = __fadd_rn(0.000100950558f,  __fmul_rn(p, w));
        p = __fadd_rn(0.00134934322f,   __fmul_rn(p, w));
        p = __fadd_rn(-0.00367342844f,  __fmul_rn(p, w));
        p = __fadd_rn(0.00573950773f,   __fmul_rn(p, w));
        p = __fadd_rn(-0.0076224613f,   __fmul_rn(p, w));
        p = __fadd_rn(0.00943887047f,   __fmul_rn(p, w));
        p = __fadd_rn(1.00167406f,      __fmul_rn(p, w));
        p = __fadd_rn(2.83297682f,      __fmul_rn(p, w));
    }
    return __fmul_rn(p, x);
}

// Fast Giles — VALUE-ONLY path (eps): FMA-contracted poly + MUFU log.
__device__ __forceinline__ float xla_erfinv_fast(float x)
{
    float w = -__logf(__fmaf_rn(-x, x, 1.0f));
    float p;
    if (w < 5.0f) {
        w = __fsub_rn(w, 2.5f);
        p = 2.81022636e-08f;
        p = __fmaf_rn(p, w, 3.43273939e-07f);
        p = __fmaf_rn(p, w, -3.5233877e-06f);
        p = __fmaf_rn(p, w, -4.39150654e-06f);
        p = __fmaf_rn(p, w, 0.00021858087f);
        p = __fmaf_rn(p, w, -0.00125372503f);
        p = __fmaf_rn(p, w, -0.00417768164f);
        p = __fmaf_rn(p, w, 0.246640727f);
        p = __fmaf_rn(p, w, 1.50140941f);
    } else {
        w = __fsub_rn(sqrtf(w), 3.0f);
        p = -0.000200214257f;
        p = __fmaf_rn(p, w, 0.000100950558f);
        p = __fmaf_rn(p, w, 0.00134934322f);
        p = __fmaf_rn(p, w, -0.00367342844f);
        p = __fmaf_rn(p, w, 0.00573950773f);
        p = __fmaf_rn(p, w, -0.0076224613f);
        p = __fmaf_rn(p, w, 0.00943887047f);
        p = __fmaf_rn(p, w, 1.00167406f);
        p = __fmaf_rn(p, w, 2.83297682f);
    }
    return __fmul_rn(p, x);
}

// Decision-coupled normal: exact forms throughout.
__device__ __forceinline__ float normal_scalar_pt(u32 k0, u32 k1, u32 one)
{
    u32 o0, o1; tf2x32(k0, k1, 0u, 0u, one, o0, o1);
    float f = bits_to_f01(o0 ^ o1);
    float u = __fmaf_rn(f, 2.0f, -0.99999994f);   // bit-identical (2f exact)
    return __fmul_rn(1.41421356237f, xla_erfinv(u));
}

__device__ __forceinline__ float uniform01_scalar_pt(u32 k0, u32 k1, u32 one)
{
    u32 o0, o1; tf2x32(k0, k1, 0u, 0u, one, o0, o1);
    return bits_to_f01(o0 ^ o1);
}

// One full Marsaglia-Tsang iteration (PRECISE decision logs). Lazy next-key.
__device__ __forceinline__ bool gamma_iter(u32 k0, u32 k1, float dd, float cc,
                                           u32 one, float &Vout)
{
    u32 xk0, xk1, uk0, uk1;
    tf2x32(k0, k1, 0u, 1u, one, xk0, xk1);   // x_key
    tf2x32(k0, k1, 0u, 2u, one, uk0, uk1);   // U_key

    float x, v;
    for (;;) {
        u32 s0, s1; tf2x32(xk0, xk1, 0u, 1u, one, s0, s1);
        x = normal_scalar_pt(s0, s1, one);
        v = __fadd_rn(1.0f, __fmul_rn(x, cc));
        if (v > 0.0f) break;
        u32 a, b; tf2x32(xk0, xk1, 0u, 0u, one, a, b); xk0 = a; xk1 = b;
    }
    float X = __fmul_rn(x, x);
    float V = __fmul_rn(__fmul_rn(v, v), v);
    float U = uniform01_scalar_pt(uk0, uk1, one);
    Vout = V;

    if (U < __fsub_rn(1.0f, __fmul_rn(0.0331f, __fmul_rn(X, X)))) return true;
    float rhs = __fadd_rn(__fmul_rn(X, 0.5f),
                __fmul_rn(dd, __fadd_rn(__fsub_rn(1.0f, V), logf(V))));
    return (logf(U) < rhs);
}

// Full gamma (boost split + loop). Dirichlet only.
__device__ float gamma_full(u32 k0, u32 k1, float dd, float cc, u32 one)
{
    { u32 a, b; tf2x32(k0, k1, 0u, 0u, one, a, b); k0 = a; k1 = b; }
    float V;
    for (;;) {
        if (gamma_iter(k0, k1, dd, cc, one, V)) break;
        u32 a, b; tf2x32(k0, k1, 0u, 0u, one, a, b); k0 = a; k1 = b;
    }
    return __fmul_rn(dd, V);
}

// ============================================================================
// Precomputed tables + KL partials
// ============================================================================
__device__ float  g_klpart[17];  // [0..15] per-block KL partials, [16] theta_div
__device__ float4 g_prm[4096];   // dd, cc, invbe, 0
__device__ float2 g_ls[4096];    // locs, scales
__device__ float2 g_dcc[64];     // Dirichlet (dd, cc) per component

__device__ __forceinline__ float digammaf_(float x)
{
    float acc = 0.0f;
    while (x < 8.0f) { acc -= __fdiv_rn(1.0f, x); x += 1.0f; }
    float ix  = __fdiv_rn(1.0f, x);
    float ix2 = ix * ix;
    float s = logf(x) - 0.5f * ix
            - ix2 * (0.0833333333f - ix2 * (0.00833333333f - ix2 * 0.00396825397f));
    return s + acc;
}

// Parallel KL: 16 blocks x 256 threads, one (k,d) element per thread.
// theta_div + Dirichlet dd/cc precompute in warp 0 of block 0.
__global__ void kl_kernel(const float* __restrict__ locs, const float* __restrict__ scales,
                          const float* __restrict__ alpha, const float* __restrict__ beta,
                          const float* __restrict__ counts)
{
    __shared__ float red[256];
    const int i = blockIdx.x * 256 + threadIdx.x;

    float lc = locs[i], sc = scales[i], al = alpha[i], be = beta[i];
    float acc = -logf(sc) + 0.5f * (sc * sc + lc * lc) - 0.5f
              + (al - 5.0f) * digammaf_(al) - lgammaf(al) + lgammaf(5.0f)
              + 5.0f * (logf(be) - logf(5.0f)) + al * (5.0f - be) / be;

    float dd = __fsub_rn(al, 0.33333334f);
    float cc = __fdiv_rn(0.33333334f, sqrtf(dd));
    g_prm[i] = make_float4(dd, cc, __fdiv_rn(1.0f, be), 0.0f);
    g_ls[i]  = make_float2(lc, sc);

    red[threadIdx.x] = acc;
    __syncthreads();
    for (int s = 128; s > 0; s >>= 1) {
        if (threadIdx.x < (unsigned)s) red[threadIdx.x] += red[threadIdx.x + s];
        __syncthreads();
    }
    if (threadIdx.x == 0) g_klpart[blockIdx.x] = red[0];

    // theta_div + Dirichlet dd/cc tables in warp 0 of block 0
    if (blockIdx.x == 0 && threadIdx.x < 32) {
        const int lane = threadIdx.x;
        // Dirichlet per-component (dd, cc): bit-identical expressions
        {
            float ck0 = counts[lane];
            float d0 = __fsub_rn(ck0, 0.33333334f);
            g_dcc[lane] = make_float2(d0, __fdiv_rn(0.33333334f, sqrtf(d0)));
            float ck1 = counts[lane + 32];
            float d1 = __fsub_rn(ck1, 0.33333334f);
            g_dcc[lane + 32] = make_float2(d1, __fdiv_rn(0.33333334f, sqrtf(d1)));
        }
        float c0p = counts[lane] + counts[lane + 32];
        float c0 = c0p;
        for (int m = 16; m; m >>= 1) c0 += __shfl_xor_sync(0xffffffffu, c0, m);
        float dg0 = digammaf_(c0);
        float lg2 = lgammaf(2.0f);
        float term = 0.0f;
        {
            float ck = counts[lane];
            term += lg2 - lgammaf(ck) + (ck - 2.0f) * (digammaf_(ck) - dg0);
        }
        {
            float ck = counts[lane + 32];
            term += lg2 - lgammaf(ck) + (ck - 2.0f) * (digammaf_(ck) - dg0);
        }
        for (int m = 16; m; m >>= 1) term += __shfl_xor_sync(0xffffffffu, term, m);
        if (lane == 0)
            g_klpart[16] = lgammaf(c0) - lgammaf(128.0f) + term;  // a0 = 2*64
    }
}

// ============================================================================
// Main loss kernel (R14 structure; Dirichlet dd/cc from precomputed table).
// ============================================================================
__global__ __launch_bounds__(256, 8) void loss_kernel(
    const float* __restrict__ x, float* __restrict__ out)
{
    const int n = blockIdx.x;
    const int t = threadIdx.x;
    const int k = t >> 2;
    const int q = t & 3;

    __shared__ float s_x[64];
    __shared__ float s_comp[64];
    __shared__ float s_gd[64];

    if (t < 64) s_x[t] = x[n * 64 + t];

    const u32 one = load_opaque_one();
    __syncthreads();

    // Deferred queue: pending log-tests [0,nt). qU/qX/qV pending-only.
    u32   qk0[16], qk1[16];
    int   qidx[16];
    float qU[16], qX[16], qV[16], qdf[16];
    int nt = 0;

    float zsum = 0.0f, lsum = 0.0f;
    float rprod = 1.0f;   // 16-product safe: r in ~[0.03, 2.4]
    const int kd_base = k * 64 + q * 16;
    const u32 i_base = (u32)n * 4096u + (u32)kd_base;

#pragma unroll 1
    for (int j = 0; j < 16; ++j) {
        const int kdidx = kd_base + j;
        const u32 i = i_base + (u32)j;

        // eps[n,k,d] — value-only: fused constant + fast erfinv
        u32 e0, e1; tf2x32(KE.a, KE.b, 0u, i, one, e0, e1);
        float fp = __uint_as_float((((e0 ^ e1) >> 9)) | 0x3f800000u); // [1,2)
        float u = __fmaf_rn(fp, 2.0f, -3.0f);
        float eps = __fmul_rn(1.41421356237f, xla_erfinv_fast(u));

        const float4 prm = g_prm[kdidx];         // dd, cc, invbe
        const float2 ls  = g_ls[kdidx];          // locs, scales
        float mu   = __fadd_rn(ls.x, __fmul_rn(ls.y, eps));
        float diff = __fsub_rn(s_x[kdidx & 63], mu);
        float diff2 = __fmul_rn(diff, diff);

        // gamma attempt
        u32 ek0, ek1, bk0, bk1, xk0, xk1, uk0, uk1;
        tf2x32(KG.a, KG.b, 0u, i, one, ek0, ek1);     // element key
        tf2x32(ek0, ek1, 0u, 0u, one, bk0, bk1);      // post-boost key
        tf2x32(bk0, bk1, 0u, 1u, one, xk0, xk1);      // x_key
        tf2x32(bk0, bk1, 0u, 2u, one, uk0, uk1);      // U_key

        float xv, vv;
        for (;;) {
            u32 s0, s1; tf2x32(xk0, xk1, 0u, 1u, one, s0, s1);
            xv = normal_scalar_pt(s0, s1, one);
            vv = __fadd_rn(1.0f, __fmul_rn(xv, prm.y));
            if (vv > 0.0f) break;
            u32 a, b; tf2x32(xk0, xk1, 0u, 0u, one, a, b); xk0 = a; xk1 = b;
        }
        float X = __fmul_rn(xv, xv);
        float V = __fmul_rn(__fmul_rn(vv, vv), vv);
        float U = uniform01_scalar_pt(uk0, uk1, one);

        if (U < __fsub_rn(1.0f, __fmul_rn(0.0331f, __fmul_rn(X, X)))) {
            float r = __fmul_rn(__fmul_rn(prm.x, V), prm.z);
            zsum += __fmul_rn(diff2, r);
            rprod = __fmul_rn(rprod, r);
        } else {
            qk0[nt] = bk0; qk1[nt] = bk1;
            qidx[nt] = kdidx;
            qU[nt] = U; qX[nt] = X; qV[nt] = V;
            qdf[nt] = diff2;
            ++nt;
        }
    }
    lsum += __logf(rprod);   // value-only; single flush

    // Phase 2: accepted r's accumulate in rprod2, logged once at the end.
    float rprod2 = 1.0f;

    // Phase 2a: dense forward sweep of pending log-tests; rejects compact to
    // [0,wr), wr <= rd (no aliasing). Decision logs stay PRECISE.
    int rd = 0, wr = 0;
    while (__any_sync(0xffffffffu, rd < nt)) {
        if (rd < nt) {
            const float4 prm = g_prm[qidx[rd]];
            float V = qV[rd], dd = prm.x;
            float rhs = __fadd_rn(__fmul_rn(qX[rd], 0.5f),
                        __fmul_rn(dd, __fadd_rn(__fsub_rn(1.0f, V), logf(V))));
            if (logf(qU[rd]) < rhs) {
                float r = __fmul_rn(__fmul_rn(dd, V), prm.z);
                zsum += __fmul_rn(qdf[rd], r);
                rprod2 = __fmul_rn(rprod2, r);
            } else {
                qk0[wr] = qk0[rd]; qk1[wr] = qk1[rd];
                qidx[wr] = qidx[rd];
                qdf[wr] = qdf[rd];
                ++wr;
            }
            ++rd;
        }
    }
    int nr = wr;

    // Phase 2b: dense full-retry drain of [0,nr)
    while (__any_sync(0xffffffffu, nr > 0)) {
        if (nr > 0) {
            int i2 = nr - 1;
            const float4 prm = g_prm[qidx[i2]];
            u32 nk0, nk1; tf2x32(qk0[i2], qk1[i2], 0u, 0u, one, nk0, nk1);
            float V;
            if (gamma_iter(nk0, nk1, prm.x, prm.y, one, V)) {
                float r = __fmul_rn(__fmul_rn(prm.x, V), prm.z);
                zsum += __fmul_rn(qdf[i2], r);
                rprod2 = __fmul_rn(rprod2, r);
                nr = i2;
            } else {
                qk0[i2] = nk0; qk1[i2] = nk1;
            }
        }
    }
    lsum += __logf(rprod2);   // __logf(1)=0 exactly for empty threads

    // reduce 4 lanes of component k
    zsum += __shfl_xor_sync(0xffffffffu, zsum, 1);
    zsum += __shfl_xor_sync(0xffffffffu, zsum, 2);
    lsum += __shfl_xor_sync(0xffffffffu, lsum, 1);
    lsum += __shfl_xor_sync(0xffffffffu, lsum, 2);

    if (q == 0) {
        float sumlogsig = -0.5f * lsum;
        s_comp[k] = -0.5f * zsum - sumlogsig - 58.81206612509905f; // 0.5*D*log(2pi)
    }

    // Dirichlet gammas: dense in warps 0-1, dd/cc from precomputed table
    if (t < 64) {
        u32 jidx = (u32)n * 64u + (u32)t;
        u32 dk0, dk1; tf2x32(KD.a, KD.b, 0u, jidx, one, dk0, dk1);
        const float2 dcc = g_dcc[t];
        s_gd[t] = gamma_full(dk0, dk1, dcc.x, dcc.y, one);
    }
    __syncthreads();

    if (t < 32) {
        float g0 = s_gd[t], g1 = s_gd[t + 32];
        float S = g0 + g1;
        for (int m = 16; m; m >>= 1) S += __shfl_xor_sync(0xffffffffu, S, m);
        float t0 = __logf(__fdiv_rn(g0, S)) + s_comp[t];      // value-only
        float t1 = __logf(__fdiv_rn(g1, S)) + s_comp[t + 32]; // value-only
        float mx = fmaxf(t0, t1);
        for (int m = 16; m; m >>= 1) mx = fmaxf(mx, __shfl_xor_sync(0xffffffffu, mx, m));
        float es = __expf(t0 - mx) + __expf(t1 - mx);         // value-only
        for (int m = 16; m; m >>= 1) es += __shfl_xor_sync(0xffffffffu, es, m);
        if (t == 0) {
            float log_lik = mx + __logf(es);                  // value-only
            float kl = 0.0f;
#pragma unroll
            for (int p = 0; p < 17; ++p) kl += g_klpart[p];
            out[n] = kl / 8192.0f - log_lik;
        }
    }
}

// ============================================================================
extern "C" void kernel_launch(void* const* d_in, const int* in_sizes, int n_in,
                              void* d_out, int out_size)
{
    (void)in_sizes; (void)n_in; (void)out_size;
    const float* x      = (const float*)d_in[0];
    const float* locs   = (const float*)d_in[1];
    const float* scales = (const float*)d_in[2];
    const float* alpha  = (const float*)d_in[3];
    const float* beta   = (const float*)d_in[4];
    const float* counts = (const float*)d_in[5];
    float* out = (float*)d_out;

    kl_kernel<<<16, 256>>>(locs, scales, alpha, beta, counts);
    loss_kernel<<<8192, 256>>>(x, out);
}